// round 1
// baseline (speedup 1.0000x reference)
#include <cuda_runtime.h>
#include <cuda_bf16.h>

// ---------------------------------------------------------------------------
// MambaLayer (bidirectional VideoMamba block), fp32, B200 sm_100a
// B=4, D_MODEL=128, L=8192, D_INNER=256, D_STATE=16, DT_RANK=8
// ---------------------------------------------------------------------------

#define BB   4
#define DM   128
#define LL   8192
#define DI   256
#define NS   16
#define DTR  8
#define NDBL 40          // dt_rank + 2*d_state
#define MTOK (BB*LL)     // 32768 tokens
#define CHUNK 64
#define NCH  (LL/CHUNK)  // 128 chunks

// ------------------------- scratch (static device mem) ---------------------
__device__ float g_xn   [MTOK*DM];        // LN1 output, [m][c]
__device__ float g_xflat[MTOK*DM];        // transposed raw x, [m][c]
__device__ float g_xz   [MTOK*2*DI];      // in_proj out: [m][0..255]=xi, [256..511]=z
__device__ float g_xc   [2][MTOK*DI];     // conv+silu per direction (seq order s)
__device__ float g_dbl  [2][MTOK*NDBL];   // x_proj out per direction
__device__ float g_ydir [2][MTOK*DI];     // gated scan output per dir (orig t order)
__device__ float g_hend [2*NCH*BB*NS*DI];
__device__ float g_P    [2*NCH*BB*NS*DI];
__device__ float g_hinit[2*NCH*BB*NS*DI];
__device__ float g_outpre[MTOK*DM];       // out_proj result before LN2

// ------------------------- helpers -----------------------------------------
__device__ __forceinline__ float softplusf(float x) {
    return (x > 20.f) ? x : __logf(1.f + __expf(x));
}
__device__ __forceinline__ float siluf(float x) {
    return __fdividef(x, 1.f + __expf(-x));
}

// ------------------------- LN1 + transpose ----------------------------------
// x: [B, DM, L] -> g_xn/g_xflat: [m=b*L+l][c], m-tile of 64 per block
__global__ void k_ln1(const float* __restrict__ x,
                      const float* __restrict__ w, const float* __restrict__ bia) {
    __shared__ float s[DM][65];
    __shared__ float rs_[4][64], rq_[4][64];
    __shared__ float mu[64], rstd[64];
    int tid = threadIdx.x;
    int m0 = blockIdx.x * 64;
    int b  = m0 / LL;
    int l0 = m0 % LL;
#pragma unroll
    for (int i = 0; i < 32; i++) {          // load 128x64 tile, coalesced over l
        int e = tid + i * 256;
        int l = e & 63, c = e >> 6;
        s[c][l] = x[(b * DM + c) * LL + l0 + l];
    }
    __syncthreads();
    {
        int tok = tid & 63, part = tid >> 6;
        float su = 0.f, sq = 0.f;
#pragma unroll
        for (int cc = 0; cc < 32; cc++) {
            float v = s[part * 32 + cc][tok];
            su += v; sq = fmaf(v, v, sq);
        }
        rs_[part][tok] = su; rq_[part][tok] = sq;
    }
    __syncthreads();
    if (tid < 64) {
        float su = rs_[0][tid] + rs_[1][tid] + rs_[2][tid] + rs_[3][tid];
        float sq = rq_[0][tid] + rq_[1][tid] + rq_[2][tid] + rq_[3][tid];
        float m = su * (1.f / DM);
        float var = sq * (1.f / DM) - m * m;
        mu[tid] = m; rstd[tid] = rsqrtf(var + 1e-5f);
    }
    __syncthreads();
#pragma unroll
    for (int i = 0; i < 32; i++) {          // write coalesced over c
        int e = tid + i * 256;
        int c = e & 127, l = e >> 7;
        float v = s[c][l];
        g_xflat[(m0 + l) * DM + c] = v;
        g_xn[(m0 + l) * DM + c] = (v - mu[l]) * rstd[l] * w[c] + bia[c];
    }
}

// ------------------------- generic NT GEMM ----------------------------------
// C[m][n] = sum_k A[m][k]*W[n][k] (+A2), BM=128 BN=64 BK=32, 256 thr, 8x4/thread
template<bool DUAL>
__global__ void gemm_nt(const float* __restrict__ A, const float* __restrict__ A2,
                        const float* __restrict__ W, float* __restrict__ C,
                        int Ka, int Nn) {
    __shared__ float As[32][128 + 4];
    __shared__ float Bs[32][64 + 4];
    int tid = threadIdx.x;
    int m0 = blockIdx.x * 128;
    int n0 = blockIdx.y * 64;
    int tx = tid & 15, ty = tid >> 4;
    float acc[8][4] = {};
    for (int k0 = 0; k0 < Ka; k0 += 32) {
#pragma unroll
        for (int i = 0; i < 16; i++) {
            int e = tid + i * 256;
            int k = e & 31, m = e >> 5;
            int gi = (m0 + m) * Ka + k0 + k;
            float v = A[gi];
            if (DUAL) v += A2[gi];
            As[k][m] = v;
        }
#pragma unroll
        for (int i = 0; i < 8; i++) {
            int e = tid + i * 256;
            int k = e & 31, n = e >> 5;
            Bs[k][n] = (n0 + n < Nn) ? W[(n0 + n) * Ka + k0 + k] : 0.f;
        }
        __syncthreads();
#pragma unroll
        for (int k = 0; k < 32; k++) {
            float4 a0 = *(const float4*)&As[k][ty * 8];
            float4 a1 = *(const float4*)&As[k][ty * 8 + 4];
            float4 bb = *(const float4*)&Bs[k][tx * 4];
            float av[8] = {a0.x, a0.y, a0.z, a0.w, a1.x, a1.y, a1.z, a1.w};
            float bv[4] = {bb.x, bb.y, bb.z, bb.w};
#pragma unroll
            for (int i = 0; i < 8; i++)
#pragma unroll
                for (int j = 0; j < 4; j++)
                    acc[i][j] = fmaf(av[i], bv[j], acc[i][j]);
        }
        __syncthreads();
    }
#pragma unroll
    for (int i = 0; i < 8; i++) {
        int m = m0 + ty * 8 + i;
        int nn = n0 + tx * 4;
#pragma unroll
        for (int j = 0; j < 4; j++)
            if (nn + j < Nn) C[m * Nn + nn + j] = acc[i][j];
    }
}

// ------------------------- depthwise causal conv + silu ---------------------
// dir 0: sequence = t; dir 1: sequence s maps to original t = L-1-s
__global__ void k_conv(const float* __restrict__ cwf, const float* __restrict__ cbf,
                       const float* __restrict__ cwb, const float* __restrict__ cbb) {
    int d = threadIdx.x;
    int s0 = blockIdx.x * 4;
    int b = blockIdx.y;
    int dir = blockIdx.z;
    const float* cw = dir ? cwb : cwf;
    const float* cb = dir ? cbb : cbf;
    float w0 = cw[d * 4], w1 = cw[d * 4 + 1], w2 = cw[d * 4 + 2], w3 = cw[d * 4 + 3];
    float bi = cb[d];
    float v[7];
#pragma unroll
    for (int j = 0; j < 7; j++) {
        int t = s0 - 3 + j;
        if (t < 0) v[j] = 0.f;
        else {
            int tt = dir ? (LL - 1 - t) : t;
            v[j] = g_xz[(b * LL + tt) * (2 * DI) + d];
        }
    }
#pragma unroll
    for (int i = 0; i < 4; i++) {
        float a = bi + w0 * v[i] + w1 * v[i + 1] + w2 * v[i + 2] + w3 * v[i + 3];
        g_xc[dir][(b * LL + s0 + i) * DI + d] = siluf(a);
    }
}

// ------------------------- scan pass 1: local chunk scan --------------------
__global__ void k_scan1(const float* __restrict__ dtw_f, const float* __restrict__ dtb_f,
                        const float* __restrict__ Alog_f,
                        const float* __restrict__ dtw_b, const float* __restrict__ dtb_b,
                        const float* __restrict__ Alog_b) {
    int ch = blockIdx.x, b = blockIdx.y, dir = blockIdx.z, d = threadIdx.x;
    const float* xc   = g_xc[dir];
    const float* dblp = g_dbl[dir];
    const float* dtw  = dir ? dtw_b : dtw_f;
    const float* Alog = dir ? Alog_b : Alog_f;
    float dtb = (dir ? dtb_b : dtb_f)[d];
    __shared__ float sd[CHUNK * NDBL];
    int t0 = ch * CHUNK;
    const float* gsrc = dblp + (size_t)(b * LL + t0) * NDBL;
    for (int i = threadIdx.x; i < CHUNK * NDBL; i += 256) sd[i] = gsrc[i];
    float Ad[NS], wdt[DTR], h[NS], p[NS];
#pragma unroll
    for (int n = 0; n < NS; n++) Ad[n] = -__expf(Alog[d * NS + n]);
#pragma unroll
    for (int i = 0; i < DTR; i++) wdt[i] = dtw[d * DTR + i];
#pragma unroll
    for (int n = 0; n < NS; n++) { h[n] = 0.f; p[n] = 1.f; }
    __syncthreads();
    for (int t = 0; t < CHUNK; t++) {
        const float* row = sd + t * NDBL;
        float dtr = dtb;
#pragma unroll
        for (int i = 0; i < DTR; i++) dtr = fmaf(wdt[i], row[i], dtr);
        float dt = softplusf(dtr);
        float xv = xc[(size_t)(b * LL + t0 + t) * DI + d];
        float cB = dt * xv;
#pragma unroll
        for (int n = 0; n < NS; n++) {
            float w = __expf(dt * Ad[n]);
            h[n] = fmaf(w, h[n], cB * row[8 + n]);
            p[n] *= w;
        }
    }
    int base = ((dir * NCH + ch) * BB + b) * NS;
#pragma unroll
    for (int n = 0; n < NS; n++) {
        g_hend[(base + n) * DI + d] = h[n];
        g_P[(base + n) * DI + d]    = p[n];
    }
}

// ------------------------- scan pass 2: chunk-level prefix ------------------
__global__ void k_scan2() {
    int d = threadIdx.x;
    int n   = blockIdx.x & 15;
    int b   = (blockIdx.x >> 4) & 3;
    int dir = blockIdx.x >> 6;
    float hs = 0.f;
    for (int ch = 0; ch < NCH; ch++) {
        int idx = (((dir * NCH + ch) * BB + b) * NS + n) * DI + d;
        g_hinit[idx] = hs;
        hs = fmaf(g_P[idx], hs, g_hend[idx]);
    }
}

// ------------------------- scan pass 3: re-scan with true h0, emit y --------
__global__ void k_scan3(const float* __restrict__ dtw_f, const float* __restrict__ dtb_f,
                        const float* __restrict__ Alog_f, const float* __restrict__ Dsk_f,
                        const float* __restrict__ dtw_b, const float* __restrict__ dtb_b,
                        const float* __restrict__ Alog_b, const float* __restrict__ Dsk_b) {
    int ch = blockIdx.x, b = blockIdx.y, dir = blockIdx.z, d = threadIdx.x;
    const float* xc   = g_xc[dir];
    const float* dblp = g_dbl[dir];
    const float* dtw  = dir ? dtw_b : dtw_f;
    const float* Alog = dir ? Alog_b : Alog_f;
    float dtb = (dir ? dtb_b : dtb_f)[d];
    float Dd  = (dir ? Dsk_b : Dsk_f)[d];
    __shared__ float sd[CHUNK * NDBL];
    int t0 = ch * CHUNK;
    const float* gsrc = dblp + (size_t)(b * LL + t0) * NDBL;
    for (int i = threadIdx.x; i < CHUNK * NDBL; i += 256) sd[i] = gsrc[i];
    float Ad[NS], wdt[DTR], h[NS];
#pragma unroll
    for (int n = 0; n < NS; n++) Ad[n] = -__expf(Alog[d * NS + n]);
#pragma unroll
    for (int i = 0; i < DTR; i++) wdt[i] = dtw[d * DTR + i];
    int base = ((dir * NCH + ch) * BB + b) * NS;
#pragma unroll
    for (int n = 0; n < NS; n++) h[n] = g_hinit[(base + n) * DI + d];
    __syncthreads();
    float* yout = g_ydir[dir];
    for (int t = 0; t < CHUNK; t++) {
        const float* row = sd + t * NDBL;
        float dtr = dtb;
#pragma unroll
        for (int i = 0; i < DTR; i++) dtr = fmaf(wdt[i], row[i], dtr);
        float dt = softplusf(dtr);
        float xv = xc[(size_t)(b * LL + t0 + t) * DI + d];
        float cB = dt * xv;
        float y = 0.f;
#pragma unroll
        for (int n = 0; n < NS; n++) {
            float w = __expf(dt * Ad[n]);
            h[n] = fmaf(w, h[n], cB * row[8 + n]);
            y = fmaf(h[n], row[24 + n], y);
        }
        int s = t0 + t;
        int torig = dir ? (LL - 1 - s) : s;
        float zv = g_xz[(size_t)(b * LL + torig) * (2 * DI) + DI + d];
        yout[(size_t)(b * LL + torig) * DI + d] = (y + xv * Dd) * siluf(zv);
    }
}

// ------------------------- LN2 + residual + transpose back ------------------
__global__ void k_ln2(const float* __restrict__ w, const float* __restrict__ bia,
                      float* __restrict__ out) {
    __shared__ float s[DM][65];
    __shared__ float rs_[4][64], rq_[4][64];
    __shared__ float mu[64], rstd[64];
    int tid = threadIdx.x;
    int m0 = blockIdx.x * 64;
    int b  = m0 / LL;
    int l0 = m0 % LL;
#pragma unroll
    for (int i = 0; i < 32; i++) {          // coalesced read over c
        int e = tid + i * 256;
        int c = e & 127, l = e >> 7;
        int gi = (m0 + l) * DM + c;
        s[c][l] = g_outpre[gi] + g_xflat[gi];
    }
    __syncthreads();
    {
        int tok = tid & 63, part = tid >> 6;
        float su = 0.f, sq = 0.f;
#pragma unroll
        for (int cc = 0; cc < 32; cc++) {
            float v = s[part * 32 + cc][tok];
            su += v; sq = fmaf(v, v, sq);
        }
        rs_[part][tok] = su; rq_[part][tok] = sq;
    }
    __syncthreads();
    if (tid < 64) {
        float su = rs_[0][tid] + rs_[1][tid] + rs_[2][tid] + rs_[3][tid];
        float sq = rq_[0][tid] + rq_[1][tid] + rq_[2][tid] + rq_[3][tid];
        float m = su * (1.f / DM);
        float var = sq * (1.f / DM) - m * m;
        mu[tid] = m; rstd[tid] = rsqrtf(var + 1e-5f);
    }
    __syncthreads();
#pragma unroll
    for (int i = 0; i < 32; i++) {          // coalesced write over l
        int e = tid + i * 256;
        int l = e & 63, c = e >> 6;
        out[(b * DM + c) * LL + l0 + l] = (s[c][l] - mu[l]) * rstd[l] * w[c] + bia[c];
    }
}

// ------------------------- launch ------------------------------------------
extern "C" void kernel_launch(void* const* d_in, const int* in_sizes, int n_in,
                              void* d_out, int out_size) {
    const float* x        = (const float*)d_in[0];
    const float* ln1_w    = (const float*)d_in[1];
    const float* ln1_b    = (const float*)d_in[2];
    const float* ln2_w    = (const float*)d_in[3];
    const float* ln2_b    = (const float*)d_in[4];
    const float* in_proj  = (const float*)d_in[5];
    const float* out_proj = (const float*)d_in[6];
    const float* conv_w_f = (const float*)d_in[7];
    const float* conv_b_f = (const float*)d_in[8];
    const float* xproj_f  = (const float*)d_in[9];
    const float* dtw_f    = (const float*)d_in[10];
    const float* dtb_f    = (const float*)d_in[11];
    const float* Alog_f   = (const float*)d_in[12];
    const float* D_f      = (const float*)d_in[13];
    const float* conv_w_b = (const float*)d_in[14];
    const float* conv_b_b = (const float*)d_in[15];
    const float* xproj_b  = (const float*)d_in[16];
    const float* dtw_b    = (const float*)d_in[17];
    const float* dtb_b    = (const float*)d_in[18];
    const float* Alog_b   = (const float*)d_in[19];
    const float* D_b      = (const float*)d_in[20];
    float* out = (float*)d_out;

    float *p_xn, *p_xz, *p_xc, *p_dbl, *p_ydir, *p_outpre;
    cudaGetSymbolAddress((void**)&p_xn,     g_xn);
    cudaGetSymbolAddress((void**)&p_xz,     g_xz);
    cudaGetSymbolAddress((void**)&p_xc,     g_xc);
    cudaGetSymbolAddress((void**)&p_dbl,    g_dbl);
    cudaGetSymbolAddress((void**)&p_ydir,   g_ydir);
    cudaGetSymbolAddress((void**)&p_outpre, g_outpre);

    // 1. LN1 + transpose
    k_ln1<<<MTOK / 64, 256>>>(x, ln1_w, ln1_b);

    // 2. in_proj: [32768,128] x [512,128]^T -> g_xz
    gemm_nt<false><<<dim3(MTOK / 128, 512 / 64), 256>>>(p_xn, nullptr, in_proj, p_xz, DM, 2 * DI);

    // 3. depthwise causal conv + silu, both directions
    k_conv<<<dim3(LL / 4, BB, 2), 256>>>(conv_w_f, conv_b_f, conv_w_b, conv_b_b);

    // 4. x_proj per direction: [32768,256] x [40,256]^T -> g_dbl
    gemm_nt<false><<<dim3(MTOK / 128, 1), 256>>>(p_xc, nullptr, xproj_f, p_dbl, DI, NDBL);
    gemm_nt<false><<<dim3(MTOK / 128, 1), 256>>>(p_xc + (size_t)MTOK * DI, nullptr, xproj_b,
                                                 p_dbl + (size_t)MTOK * NDBL, DI, NDBL);

    // 5-7. chunked selective scan
    k_scan1<<<dim3(NCH, BB, 2), 256>>>(dtw_f, dtb_f, Alog_f, dtw_b, dtb_b, Alog_b);
    k_scan2<<<2 * BB * NS, 256>>>();
    k_scan3<<<dim3(NCH, BB, 2), 256>>>(dtw_f, dtb_f, Alog_f, D_f, dtw_b, dtb_b, Alog_b, D_b);

    // 8. out_proj on (y_f + y_b): [32768,256] x [128,256]^T -> g_outpre
    gemm_nt<true><<<dim3(MTOK / 128, DM / 64), 256>>>(p_ydir, p_ydir + (size_t)MTOK * DI,
                                                      out_proj, p_outpre, DI, DM);

    // 9. residual + LN2 + transpose back
    k_ln2<<<MTOK / 64, 256>>>(ln2_w, ln2_b, out);
}

// round 2
// speedup vs baseline: 1.0681x; 1.0681x over previous
#include <cuda_runtime.h>

// ---------------------------------------------------------------------------
// MambaLayer (bidirectional VideoMamba block), fp32, B200 sm_100a  — round 2
// B=4, D_MODEL=128, L=8192, D_INNER=256, D_STATE=16, DT_RANK=8
// ---------------------------------------------------------------------------

#define BB   4
#define DM   128
#define LL   8192
#define DI   256
#define NS   16
#define DTR  8
#define NDBL 40
#define MTOK (BB*LL)
#define CHUNK 64
#define NCH  (LL/CHUNK)

// ------------------------- scratch (static device mem) ---------------------
__device__ float g_xn    [MTOK*DM];
__device__ float g_xflat [MTOK*DM];
__device__ float g_xz    [MTOK*2*DI];
__device__ float g_dbl   [2][MTOK*NDBL];
__device__ float g_ydir  [2][MTOK*DI];
__device__ float g_hend  [2*NCH*BB*NS*DI];
__device__ float g_P     [2*NCH*BB*NS*DI];
__device__ float g_hinit [2*NCH*BB*NS*DI];
__device__ float g_outpre[MTOK*DM];

// ------------------------- helpers -----------------------------------------
__device__ __forceinline__ float softplusf(float x) {
    return (x > 20.f) ? x : __logf(1.f + __expf(x));
}
__device__ __forceinline__ float siluf(float x) {
    return __fdividef(x, 1.f + __expf(-x));
}

// ------------------------- LN1 + transpose ----------------------------------
__global__ void k_ln1(const float* __restrict__ x,
                      const float* __restrict__ w, const float* __restrict__ bia) {
    __shared__ float s[DM][65];
    __shared__ float rs_[4][64], rq_[4][64];
    __shared__ float mu[64], rstd[64];
    int tid = threadIdx.x;
    int m0 = blockIdx.x * 64;
    int b  = m0 / LL;
    int l0 = m0 % LL;
#pragma unroll
    for (int i = 0; i < 32; i++) {
        int e = tid + i * 256;
        int l = e & 63, c = e >> 6;
        s[c][l] = x[(b * DM + c) * LL + l0 + l];
    }
    __syncthreads();
    {
        int tok = tid & 63, part = tid >> 6;
        float su = 0.f, sq = 0.f;
#pragma unroll
        for (int cc = 0; cc < 32; cc++) {
            float v = s[part * 32 + cc][tok];
            su += v; sq = fmaf(v, v, sq);
        }
        rs_[part][tok] = su; rq_[part][tok] = sq;
    }
    __syncthreads();
    if (tid < 64) {
        float su = rs_[0][tid] + rs_[1][tid] + rs_[2][tid] + rs_[3][tid];
        float sq = rq_[0][tid] + rq_[1][tid] + rq_[2][tid] + rq_[3][tid];
        float m = su * (1.f / DM);
        float var = sq * (1.f / DM) - m * m;
        mu[tid] = m; rstd[tid] = rsqrtf(var + 1e-5f);
    }
    __syncthreads();
#pragma unroll
    for (int i = 0; i < 32; i++) {
        int e = tid + i * 256;
        int c = e & 127, l = e >> 7;
        float v = s[c][l];
        g_xflat[(m0 + l) * DM + c] = v;
        g_xn[(m0 + l) * DM + c] = (v - mu[l]) * rstd[l] * w[c] + bia[c];
    }
}

// ------------------------- 128x128 double-buffered GEMM ---------------------
// C[m][n] = sum_k A[m][k]*W[n][k]  (A optionally = A + A2), row-major.
template<int KTOT, bool DUAL>
__global__ __launch_bounds__(256) void gemm128(
        const float* __restrict__ A, const float* __restrict__ A2,
        const float* __restrict__ W, float* __restrict__ C, int Nn) {
    __shared__ float As[2][16][132];
    __shared__ float Bs[2][16][132];
    const int tid = threadIdx.x;
    const int m0 = blockIdx.x * 128, n0 = blockIdx.y * 128;
    const int tx = tid & 15, ty = tid >> 4;
    const int lm = tid & 127;
    const int lk4 = (tid >> 7) * 2;      // {0,2}
    float acc[8][8] = {};
    float4 ra[2], rb[2];

    auto loadTile = [&](int k0) {
#pragma unroll
        for (int r = 0; r < 2; r++) {
            int k = k0 + (lk4 + r) * 4;
            ra[r] = *(const float4*)&A[(size_t)(m0 + lm) * KTOT + k];
            if (DUAL) {
                float4 t2 = *(const float4*)&A2[(size_t)(m0 + lm) * KTOT + k];
                ra[r].x += t2.x; ra[r].y += t2.y; ra[r].z += t2.z; ra[r].w += t2.w;
            }
            rb[r] = *(const float4*)&W[(size_t)(n0 + lm) * KTOT + k];
        }
    };
    auto storeTile = [&](int buf) {
#pragma unroll
        for (int r = 0; r < 2; r++) {
            int kb = (lk4 + r) * 4;
            As[buf][kb + 0][lm] = ra[r].x; As[buf][kb + 1][lm] = ra[r].y;
            As[buf][kb + 2][lm] = ra[r].z; As[buf][kb + 3][lm] = ra[r].w;
            Bs[buf][kb + 0][lm] = rb[r].x; Bs[buf][kb + 1][lm] = rb[r].y;
            Bs[buf][kb + 2][lm] = rb[r].z; Bs[buf][kb + 3][lm] = rb[r].w;
        }
    };

    constexpr int NT = KTOT / 16;
    loadTile(0);
    storeTile(0);
    __syncthreads();
#pragma unroll
    for (int t = 0; t < NT; t++) {
        int cur = t & 1;
        if (t + 1 < NT) loadTile((t + 1) * 16);
#pragma unroll
        for (int k = 0; k < 16; k++) {
            float4 a0 = *(const float4*)&As[cur][k][ty * 8];
            float4 a1 = *(const float4*)&As[cur][k][ty * 8 + 4];
            float4 b0 = *(const float4*)&Bs[cur][k][tx * 8];
            float4 b1 = *(const float4*)&Bs[cur][k][tx * 8 + 4];
            float av[8] = {a0.x, a0.y, a0.z, a0.w, a1.x, a1.y, a1.z, a1.w};
            float bv[8] = {b0.x, b0.y, b0.z, b0.w, b1.x, b1.y, b1.z, b1.w};
#pragma unroll
            for (int i = 0; i < 8; i++)
#pragma unroll
                for (int j = 0; j < 8; j++)
                    acc[i][j] = fmaf(av[i], bv[j], acc[i][j]);
        }
        if (t + 1 < NT) {
            storeTile(cur ^ 1);
            __syncthreads();
        }
    }
#pragma unroll
    for (int i = 0; i < 8; i++) {
        float* cp = &C[(size_t)(m0 + ty * 8 + i) * Nn + n0 + tx * 8];
        float4 c0 = {acc[i][0], acc[i][1], acc[i][2], acc[i][3]};
        float4 c1 = {acc[i][4], acc[i][5], acc[i][6], acc[i][7]};
        *(float4*)cp = c0;
        *(float4*)(cp + 4) = c1;
    }
}

// ------------------------- x_proj with fused conv+silu ----------------------
// dbl[dir][m][0..39] = silu(convdir(xz_xi))[m][:] @ xproj_dir^T
__global__ __launch_bounds__(256) void k_xproj(
        const float* __restrict__ xproj_f, const float* __restrict__ xproj_b,
        const float* __restrict__ cwf, const float* __restrict__ cbf,
        const float* __restrict__ cwb, const float* __restrict__ cbb) {
    int m0 = blockIdx.x * 128;
    int dir = blockIdx.y;
    int b = m0 >> 13, s0 = m0 & (LL - 1);
    const float* xp = dir ? xproj_b : xproj_f;
    const float* cw = dir ? cwb : cwf;
    const float* cb = dir ? cbb : cbf;
    __shared__ float xcs[64][133];    // [k-channel][token]
    __shared__ float ws[64][41];      // [k-channel][n]
    int tid = threadIdx.x;
    int cc = tid & 63, seg = tid >> 6;       // conv producer mapping
    int ty = tid >> 3, tx = tid & 7;         // gemm mapping: 32x4 tokens, 8x5 outs
    float acc[4][5] = {};
    const float* xzb = g_xz + (size_t)b * LL * 512;

    for (int k0 = 0; k0 < 256; k0 += 64) {
        for (int i = tid; i < 64 * 40; i += 256) {
            int k = i / 40, n = i - k * 40;
            ws[k][n] = xp[n * 256 + k0 + k];
        }
        {
            int d = k0 + cc;
            float w0 = cw[d*4], w1 = cw[d*4+1], w2 = cw[d*4+2], w3 = cw[d*4+3];
            float bi = cb[d];
            int sbase = s0 + seg * 32;
            const float* xzd = xzb + d;
            float v1 = (sbase - 3 >= 0) ? xzd[(size_t)(dir ? (LL-1-(sbase-3)) : (sbase-3)) * 512] : 0.f;
            float v2 = (sbase - 2 >= 0) ? xzd[(size_t)(dir ? (LL-1-(sbase-2)) : (sbase-2)) * 512] : 0.f;
            float v3 = (sbase - 1 >= 0) ? xzd[(size_t)(dir ? (LL-1-(sbase-1)) : (sbase-1)) * 512] : 0.f;
#pragma unroll 4
            for (int j = 0; j < 32; j++) {
                int s = sbase + j;
                float v0 = v1; v1 = v2; v2 = v3;
                v3 = xzd[(size_t)(dir ? (LL-1-s) : s) * 512];
                float a = bi + w0*v0 + w1*v1 + w2*v2 + w3*v3;
                xcs[cc][seg * 32 + j] = siluf(a);
            }
        }
        __syncthreads();
#pragma unroll 8
        for (int k = 0; k < 64; k++) {
            float a0 = xcs[k][ty*4], a1 = xcs[k][ty*4+1], a2 = xcs[k][ty*4+2], a3 = xcs[k][ty*4+3];
            float bv[5];
#pragma unroll
            for (int j = 0; j < 5; j++) bv[j] = ws[k][tx*5 + j];
#pragma unroll
            for (int j = 0; j < 5; j++) {
                acc[0][j] = fmaf(a0, bv[j], acc[0][j]);
                acc[1][j] = fmaf(a1, bv[j], acc[1][j]);
                acc[2][j] = fmaf(a2, bv[j], acc[2][j]);
                acc[3][j] = fmaf(a3, bv[j], acc[3][j]);
            }
        }
        __syncthreads();
    }
    float* outp = g_dbl[dir];
#pragma unroll
    for (int i = 0; i < 4; i++)
#pragma unroll
        for (int j = 0; j < 5; j++)
            outp[(size_t)(m0 + ty * 4 + i) * NDBL + tx * 5 + j] = acc[i][j];
}

// ------------------------- scan pass 1 (fused conv, fast exp) ---------------
__global__ void k_scan1(const float* __restrict__ dtw_f, const float* __restrict__ dtb_f,
                        const float* __restrict__ Alog_f,
                        const float* __restrict__ dtw_b, const float* __restrict__ dtb_b,
                        const float* __restrict__ Alog_b,
                        const float* __restrict__ cwf, const float* __restrict__ cbf,
                        const float* __restrict__ cwb, const float* __restrict__ cbb) {
    int ch = blockIdx.x, b = blockIdx.y, dir = blockIdx.z, d = threadIdx.x;
    const float* dtw  = dir ? dtw_b : dtw_f;
    const float* Alog = dir ? Alog_b : Alog_f;
    const float* cw   = dir ? cwb : cwf;
    float dtb = (dir ? dtb_b : dtb_f)[d];
    float cbi = (dir ? cbb : cbf)[d];
    __shared__ float sd[CHUNK * NDBL];
    int t0 = ch * CHUNK;
    const float* gsrc = g_dbl[dir] + (size_t)(b * LL + t0) * NDBL;
    for (int i = threadIdx.x; i < CHUNK * NDBL; i += 256) sd[i] = gsrc[i];
    float Ad[NS], wdt[DTR], h[NS];
    bool fast = true;
#pragma unroll
    for (int n = 0; n < NS; n++) {
        Ad[n] = -__expf(Alog[d * NS + n]);
        fast = fast && (fabsf(Ad[n] + (float)(n + 1)) <= 1e-5f * (n + 1));
    }
#pragma unroll
    for (int i = 0; i < DTR; i++) wdt[i] = dtw[d * DTR + i];
#pragma unroll
    for (int n = 0; n < NS; n++) h[n] = 0.f;
    float cw0 = cw[d*4], cw1 = cw[d*4+1], cw2 = cw[d*4+2], cw3 = cw[d*4+3];
    const float* xzd = g_xz + (size_t)b * LL * 512 + d;
    float S = 0.f;
    float v1 = (t0-3 >= 0) ? xzd[(size_t)(dir ? (LL-1-(t0-3)) : (t0-3)) * 512] : 0.f;
    float v2 = (t0-2 >= 0) ? xzd[(size_t)(dir ? (LL-1-(t0-2)) : (t0-2)) * 512] : 0.f;
    float v3 = (t0-1 >= 0) ? xzd[(size_t)(dir ? (LL-1-(t0-1)) : (t0-1)) * 512] : 0.f;
    __syncthreads();
    if (fast) {
#pragma unroll 4
        for (int t = 0; t < CHUNK; t++) {
            int s = t0 + t;
            float v0 = v1; v1 = v2; v2 = v3;
            v3 = xzd[(size_t)(dir ? (LL-1-s) : s) * 512];
            float xv = siluf(cbi + cw0*v0 + cw1*v1 + cw2*v2 + cw3*v3);
            const float* row = sd + t * NDBL;
            float dtr = dtb;
#pragma unroll
            for (int i = 0; i < DTR; i++) dtr = fmaf(wdt[i], row[i], dtr);
            float dt = softplusf(dtr);
            S += dt;
            float cB = dt * xv;
            float r = __expf(-dt);
            float w = r;
#pragma unroll
            for (int n = 0; n < NS; n++) {
                h[n] = fmaf(w, h[n], cB * row[8 + n]);
                w *= r;
            }
        }
    } else {
#pragma unroll 2
        for (int t = 0; t < CHUNK; t++) {
            int s = t0 + t;
            float v0 = v1; v1 = v2; v2 = v3;
            v3 = xzd[(size_t)(dir ? (LL-1-s) : s) * 512];
            float xv = siluf(cbi + cw0*v0 + cw1*v1 + cw2*v2 + cw3*v3);
            const float* row = sd + t * NDBL;
            float dtr = dtb;
#pragma unroll
            for (int i = 0; i < DTR; i++) dtr = fmaf(wdt[i], row[i], dtr);
            float dt = softplusf(dtr);
            S += dt;
            float cB = dt * xv;
#pragma unroll
            for (int n = 0; n < NS; n++) {
                float w = __expf(dt * Ad[n]);
                h[n] = fmaf(w, h[n], cB * row[8 + n]);
            }
        }
    }
    int base = ((dir * NCH + ch) * BB + b) * NS;
#pragma unroll
    for (int n = 0; n < NS; n++) {
        g_hend[(base + n) * DI + d] = h[n];
        g_P[(base + n) * DI + d]    = __expf(Ad[n] * S);   // prod_t exp(dt A) = exp(A*sum dt)
    }
}

// ------------------------- scan pass 2: chunk-level prefix ------------------
__global__ void k_scan2() {
    int d = threadIdx.x;
    int n   = blockIdx.x & 15;
    int b   = (blockIdx.x >> 4) & 3;
    int dir = blockIdx.x >> 6;
    float hs = 0.f;
    for (int ch = 0; ch < NCH; ch++) {
        int idx = (((dir * NCH + ch) * BB + b) * NS + n) * DI + d;
        g_hinit[idx] = hs;
        hs = fmaf(g_P[idx], hs, g_hend[idx]);
    }
}

// ------------------------- scan pass 3 (fused conv, fast exp, emit y) -------
__global__ void k_scan3(const float* __restrict__ dtw_f, const float* __restrict__ dtb_f,
                        const float* __restrict__ Alog_f, const float* __restrict__ Dsk_f,
                        const float* __restrict__ dtw_b, const float* __restrict__ dtb_b,
                        const float* __restrict__ Alog_b, const float* __restrict__ Dsk_b,
                        const float* __restrict__ cwf, const float* __restrict__ cbf,
                        const float* __restrict__ cwb, const float* __restrict__ cbb) {
    int ch = blockIdx.x, b = blockIdx.y, dir = blockIdx.z, d = threadIdx.x;
    const float* dtw  = dir ? dtw_b : dtw_f;
    const float* Alog = dir ? Alog_b : Alog_f;
    const float* cw   = dir ? cwb : cwf;
    float dtb = (dir ? dtb_b : dtb_f)[d];
    float cbi = (dir ? cbb : cbf)[d];
    float Dd  = (dir ? Dsk_b : Dsk_f)[d];
    __shared__ float sd[CHUNK * NDBL];
    int t0 = ch * CHUNK;
    const float* gsrc = g_dbl[dir] + (size_t)(b * LL + t0) * NDBL;
    for (int i = threadIdx.x; i < CHUNK * NDBL; i += 256) sd[i] = gsrc[i];
    float Ad[NS], wdt[DTR], h[NS];
    bool fast = true;
#pragma unroll
    for (int n = 0; n < NS; n++) {
        Ad[n] = -__expf(Alog[d * NS + n]);
        fast = fast && (fabsf(Ad[n] + (float)(n + 1)) <= 1e-5f * (n + 1));
    }
#pragma unroll
    for (int i = 0; i < DTR; i++) wdt[i] = dtw[d * DTR + i];
    int base = ((dir * NCH + ch) * BB + b) * NS;
#pragma unroll
    for (int n = 0; n < NS; n++) h[n] = g_hinit[(base + n) * DI + d];
    float cw0 = cw[d*4], cw1 = cw[d*4+1], cw2 = cw[d*4+2], cw3 = cw[d*4+3];
    const float* xzd = g_xz + (size_t)b * LL * 512 + d;        // xi half
    const float* xzz = xzd + DI;                                // z half
    float* yout = g_ydir[dir] + (size_t)b * LL * DI + d;
    float v1 = (t0-3 >= 0) ? xzd[(size_t)(dir ? (LL-1-(t0-3)) : (t0-3)) * 512] : 0.f;
    float v2 = (t0-2 >= 0) ? xzd[(size_t)(dir ? (LL-1-(t0-2)) : (t0-2)) * 512] : 0.f;
    float v3 = (t0-1 >= 0) ? xzd[(size_t)(dir ? (LL-1-(t0-1)) : (t0-1)) * 512] : 0.f;
    __syncthreads();
    if (fast) {
#pragma unroll 4
        for (int t = 0; t < CHUNK; t++) {
            int s = t0 + t;
            int torig = dir ? (LL - 1 - s) : s;
            float v0 = v1; v1 = v2; v2 = v3;
            v3 = xzd[(size_t)torig * 512];
            float xv = siluf(cbi + cw0*v0 + cw1*v1 + cw2*v2 + cw3*v3);
            const float* row = sd + t * NDBL;
            float dtr = dtb;
#pragma unroll
            for (int i = 0; i < DTR; i++) dtr = fmaf(wdt[i], row[i], dtr);
            float dt = softplusf(dtr);
            float cB = dt * xv;
            float r = __expf(-dt);
            float w = r;
            float y = 0.f;
#pragma unroll
            for (int n = 0; n < NS; n++) {
                h[n] = fmaf(w, h[n], cB * row[8 + n]);
                y = fmaf(h[n], row[24 + n], y);
                w *= r;
            }
            float zv = xzz[(size_t)torig * 512];
            yout[(size_t)torig * DI] = (y + xv * Dd) * siluf(zv);
        }
    } else {
#pragma unroll 2
        for (int t = 0; t < CHUNK; t++) {
            int s = t0 + t;
            int torig = dir ? (LL - 1 - s) : s;
            float v0 = v1; v1 = v2; v2 = v3;
            v3 = xzd[(size_t)torig * 512];
            float xv = siluf(cbi + cw0*v0 + cw1*v1 + cw2*v2 + cw3*v3);
            const float* row = sd + t * NDBL;
            float dtr = dtb;
#pragma unroll
            for (int i = 0; i < DTR; i++) dtr = fmaf(wdt[i], row[i], dtr);
            float dt = softplusf(dtr);
            float cB = dt * xv;
            float y = 0.f;
#pragma unroll
            for (int n = 0; n < NS; n++) {
                float w = __expf(dt * Ad[n]);
                h[n] = fmaf(w, h[n], cB * row[8 + n]);
                y = fmaf(h[n], row[24 + n], y);
            }
            float zv = xzz[(size_t)torig * 512];
            yout[(size_t)torig * DI] = (y + xv * Dd) * siluf(zv);
        }
    }
}

// ------------------------- LN2 + residual + transpose back ------------------
__global__ void k_ln2(const float* __restrict__ w, const float* __restrict__ bia,
                      float* __restrict__ out) {
    __shared__ float s[DM][65];
    __shared__ float rs_[4][64], rq_[4][64];
    __shared__ float mu[64], rstd[64];
    int tid = threadIdx.x;
    int m0 = blockIdx.x * 64;
    int b  = m0 / LL;
    int l0 = m0 % LL;
#pragma unroll
    for (int i = 0; i < 32; i++) {
        int e = tid + i * 256;
        int c = e & 127, l = e >> 7;
        int gi = (m0 + l) * DM + c;
        s[c][l] = g_outpre[gi] + g_xflat[gi];
    }
    __syncthreads();
    {
        int tok = tid & 63, part = tid >> 6;
        float su = 0.f, sq = 0.f;
#pragma unroll
        for (int cc = 0; cc < 32; cc++) {
            float v = s[part * 32 + cc][tok];
            su += v; sq = fmaf(v, v, sq);
        }
        rs_[part][tok] = su; rq_[part][tok] = sq;
    }
    __syncthreads();
    if (tid < 64) {
        float su = rs_[0][tid] + rs_[1][tid] + rs_[2][tid] + rs_[3][tid];
        float sq = rq_[0][tid] + rq_[1][tid] + rq_[2][tid] + rq_[3][tid];
        float m = su * (1.f / DM);
        float var = sq * (1.f / DM) - m * m;
        mu[tid] = m; rstd[tid] = rsqrtf(var + 1e-5f);
    }
    __syncthreads();
#pragma unroll
    for (int i = 0; i < 32; i++) {
        int e = tid + i * 256;
        int l = e & 63, c = e >> 6;
        out[(b * DM + c) * LL + l0 + l] = (s[c][l] - mu[l]) * rstd[l] * w[c] + bia[c];
    }
}

// ------------------------- launch ------------------------------------------
extern "C" void kernel_launch(void* const* d_in, const int* in_sizes, int n_in,
                              void* d_out, int out_size) {
    const float* x        = (const float*)d_in[0];
    const float* ln1_w    = (const float*)d_in[1];
    const float* ln1_b    = (const float*)d_in[2];
    const float* ln2_w    = (const float*)d_in[3];
    const float* ln2_b    = (const float*)d_in[4];
    const float* in_proj  = (const float*)d_in[5];
    const float* out_proj = (const float*)d_in[6];
    const float* conv_w_f = (const float*)d_in[7];
    const float* conv_b_f = (const float*)d_in[8];
    const float* xproj_f  = (const float*)d_in[9];
    const float* dtw_f    = (const float*)d_in[10];
    const float* dtb_f    = (const float*)d_in[11];
    const float* Alog_f   = (const float*)d_in[12];
    const float* D_f      = (const float*)d_in[13];
    const float* conv_w_b = (const float*)d_in[14];
    const float* conv_b_b = (const float*)d_in[15];
    const float* xproj_b  = (const float*)d_in[16];
    const float* dtw_b    = (const float*)d_in[17];
    const float* dtb_b    = (const float*)d_in[18];
    const float* Alog_b   = (const float*)d_in[19];
    const float* D_b      = (const float*)d_in[20];
    float* out = (float*)d_out;

    float *p_xn, *p_xz, *p_ydir, *p_outpre;
    cudaGetSymbolAddress((void**)&p_xn,     g_xn);
    cudaGetSymbolAddress((void**)&p_xz,     g_xz);
    cudaGetSymbolAddress((void**)&p_ydir,   g_ydir);
    cudaGetSymbolAddress((void**)&p_outpre, g_outpre);

    // 1. LN1 + transpose
    k_ln1<<<MTOK / 64, 256>>>(x, ln1_w, ln1_b);

    // 2. in_proj: [32768,128] x [512,128]^T -> g_xz
    gemm128<DM, false><<<dim3(MTOK / 128, 4), 256>>>(p_xn, nullptr, in_proj, p_xz, 2 * DI);

    // 3. x_proj (conv+silu fused), both directions
    k_xproj<<<dim3(MTOK / 128, 2), 256>>>(xproj_f, xproj_b,
                                          conv_w_f, conv_b_f, conv_w_b, conv_b_b);

    // 4-6. chunked selective scan (conv fused, exp fast path)
    k_scan1<<<dim3(NCH, BB, 2), 256>>>(dtw_f, dtb_f, Alog_f, dtw_b, dtb_b, Alog_b,
                                       conv_w_f, conv_b_f, conv_w_b, conv_b_b);
    k_scan2<<<2 * BB * NS, 256>>>();
    k_scan3<<<dim3(NCH, BB, 2), 256>>>(dtw_f, dtb_f, Alog_f, D_f, dtw_b, dtb_b, Alog_b, D_b,
                                       conv_w_f, conv_b_f, conv_w_b, conv_b_b);

    // 7. out_proj on (y_f + y_b): [32768,256] x [128,256]^T -> g_outpre
    gemm128<DI, true><<<dim3(MTOK / 128, 1), 256>>>(
        (const float*)p_ydir, (const float*)p_ydir + (size_t)MTOK * DI,
        out_proj, p_outpre, DM);

    // 8. residual + LN2 + transpose back
    k_ln2<<<MTOK / 64, 256>>>(ln2_w, ln2_b, out);
}

// round 6
// speedup vs baseline: 1.2703x; 1.1893x over previous
#include <cuda_runtime.h>
#include <cuda_bf16.h>
#include <cstdint>

// ---------------------------------------------------------------------------
// MambaLayer (bidirectional VideoMamba), B200 sm_100 (portable PTX) — round 6
// (round-4 source, third submission after repeated broker failures)
// mma.sync bf16-split GEMMs + MUFU-free chunked scan
// ---------------------------------------------------------------------------

#define BB   4
#define DM   128
#define LL   8192
#define DI   256
#define NS   16
#define DTR  8
#define NDBL 40
#define MTOK (BB*LL)
#define CHUNK 64
#define NCH  (LL/CHUNK)

// ------------------------- scratch (static device mem) ---------------------
__device__ float          g_xflat [MTOK*DM];
__device__ __nv_bfloat16  g_xnh   [MTOK*DM];
__device__ __nv_bfloat16  g_xnl   [MTOK*DM];
__device__ float          g_xz    [MTOK*2*DI];
__device__ float          g_dbl   [2][MTOK*NDBL];
__device__ float          g_xc    [2][MTOK*DI];
__device__ float2         g_rcb   [2][MTOK*DI];
__device__ float          g_ydir  [2][MTOK*DI];
__device__ __nv_bfloat16  g_yh    [MTOK*DI];
__device__ __nv_bfloat16  g_yl    [MTOK*DI];
__device__ float          g_hend  [2*NCH*BB*NS*DI];
__device__ float          g_P     [2*NCH*BB*NS*DI];
__device__ float          g_hinit [2*NCH*BB*NS*DI];
__device__ float          g_outpre[MTOK*DM];
__device__ __nv_bfloat16  g_wih[512*128], g_wil[512*128];
__device__ __nv_bfloat16  g_woh[128*256], g_wol[128*256];

// ------------------------- math helpers -------------------------------------
__device__ __forceinline__ float siluf(float x) {
    return __fdividef(x, 1.f + __expf(-x));
}
__device__ __forceinline__ void mkpow(float r, float* w) {
    float r2 = r * r, r3 = r2 * r, r4 = r2 * r2;
    float r5 = r4 * r, r6 = r4 * r2, r7 = r4 * r3, r8 = r4 * r4;
    w[0]=r;  w[1]=r2; w[2]=r3; w[3]=r4; w[4]=r5; w[5]=r6; w[6]=r7; w[7]=r8;
    w[8]=r8*r; w[9]=r8*r2; w[10]=r8*r3; w[11]=r8*r4;
    w[12]=r8*r5; w[13]=r8*r6; w[14]=r8*r7; w[15]=r8*r8;
}
__device__ __forceinline__ void bsplit(float v, __nv_bfloat16& hi, __nv_bfloat16& lo) {
    hi = __float2bfloat16(v);
    lo = __float2bfloat16(v - __bfloat162float(hi));
}

// ------------------------- weight convert -----------------------------------
__global__ void k_wconv(const float* __restrict__ wi, const float* __restrict__ wo) {
    int i = blockIdx.x * 256 + threadIdx.x;
    if (i < 512 * 128) bsplit(wi[i], g_wih[i], g_wil[i]);
    int j = i - 512 * 128;
    if (j >= 0 && j < 128 * 256) bsplit(wo[j], g_woh[j], g_wol[j]);
}

// ------------------------- LN1 + transpose + bf16 split ---------------------
__global__ void k_ln1(const float* __restrict__ x,
                      const float* __restrict__ w, const float* __restrict__ bia) {
    __shared__ float s[DM][65];
    __shared__ float rs_[4][64], rq_[4][64];
    __shared__ float mu[64], rstd[64];
    int tid = threadIdx.x;
    int m0 = blockIdx.x * 64;
    int b  = m0 / LL;
    int l0 = m0 % LL;
#pragma unroll
    for (int i = 0; i < 32; i++) {
        int e = tid + i * 256;
        int l = e & 63, c = e >> 6;
        s[c][l] = x[(b * DM + c) * LL + l0 + l];
    }
    __syncthreads();
    {
        int tok = tid & 63, part = tid >> 6;
        float su = 0.f, sq = 0.f;
#pragma unroll
        for (int cc = 0; cc < 32; cc++) {
            float v = s[part * 32 + cc][tok];
            su += v; sq = fmaf(v, v, sq);
        }
        rs_[part][tok] = su; rq_[part][tok] = sq;
    }
    __syncthreads();
    if (tid < 64) {
        float su = rs_[0][tid] + rs_[1][tid] + rs_[2][tid] + rs_[3][tid];
        float sq = rq_[0][tid] + rq_[1][tid] + rq_[2][tid] + rq_[3][tid];
        float m = su * (1.f / DM);
        float var = sq * (1.f / DM) - m * m;
        mu[tid] = m; rstd[tid] = rsqrtf(var + 1e-5f);
    }
    __syncthreads();
#pragma unroll
    for (int i = 0; i < 32; i++) {
        int e = tid + i * 256;
        int c = e & 127, l = e >> 7;
        float v = s[c][l];
        int gi = (m0 + l) * DM + c;
        g_xflat[gi] = v;
        float vn = (v - mu[l]) * rstd[l] * w[c] + bia[c];
        bsplit(vn, g_xnh[gi], g_xnl[gi]);
    }
}

// ------------------------- mma.sync bf16-split GEMM -------------------------
// C[m][n] = (Ah+Al)[m][K] . (Bh+Bl)[n][K]^T  via  AhBh + AhBl + AlBh
// BM=128 BN=128 BK=32, 8 warps (2x4), warp tile 64x32, m16n8k16
__device__ __forceinline__ void mma16816(float* c, const uint32_t* a, const uint32_t* b) {
    asm volatile(
        "mma.sync.aligned.m16n8k16.row.col.f32.bf16.bf16.f32 "
        "{%0,%1,%2,%3}, {%4,%5,%6,%7}, {%8,%9}, {%0,%1,%2,%3};"
        : "+f"(c[0]), "+f"(c[1]), "+f"(c[2]), "+f"(c[3])
        : "r"(a[0]), "r"(a[1]), "r"(a[2]), "r"(a[3]), "r"(b[0]), "r"(b[1]));
}

template<int KTOT>
__global__ __launch_bounds__(256) void gemm_mma(
        const __nv_bfloat16* __restrict__ Ah, const __nv_bfloat16* __restrict__ Al,
        const __nv_bfloat16* __restrict__ Bh, const __nv_bfloat16* __restrict__ Bl,
        float* __restrict__ C, int Nn) {
    __shared__ uint32_t As[2][128][18];   // [hi/lo][row][b32 col, 16 used]
    __shared__ uint32_t Bs[2][128][18];
    const int tid = threadIdx.x;
    const int m0 = blockIdx.x * 128, n0 = blockIdx.y * 128;
    const int wid = tid >> 5, lane = tid & 31;
    const int wm0 = (wid & 1) * 64, wn0 = (wid >> 1) * 32;
    const int gr = lane >> 2, cp = lane & 3;
    float acc[4][4][4] = {};

    const int lrow = tid >> 1, lhalf = tid & 1;
    for (int k0 = 0; k0 < KTOT; k0 += 32) {
#pragma unroll
        for (int sel = 0; sel < 4; sel++) {
            const __nv_bfloat16* src = (sel == 0) ? Ah : (sel == 1) ? Al
                                     : (sel == 2) ? Bh : Bl;
            const int r0 = (sel < 2) ? m0 : n0;
            uint32_t (*dst)[18] = (sel < 2) ? As[sel] : Bs[sel - 2];
            const uint4* gp = (const uint4*)&src[(size_t)(r0 + lrow) * KTOT + k0 + lhalf * 16];
            uint4 v0 = gp[0], v1 = gp[1];
            uint32_t* d = &dst[lrow][lhalf * 8];
            d[0] = v0.x; d[1] = v0.y; d[2] = v0.z; d[3] = v0.w;
            d[4] = v1.x; d[5] = v1.y; d[6] = v1.z; d[7] = v1.w;
        }
        __syncthreads();
#pragma unroll
        for (int pass = 0; pass < 3; pass++) {
            uint32_t (*pA)[18] = As[pass == 2 ? 1 : 0];
            uint32_t (*pB)[18] = Bs[pass == 1 ? 1 : 0];
#pragma unroll
            for (int k16 = 0; k16 < 2; k16++) {
                const int kp = k16 * 8;
                uint32_t a[4][4], bf[4][2];
#pragma unroll
                for (int i = 0; i < 4; i++) {
                    int rbase = wm0 + 16 * i;
                    a[i][0] = pA[rbase + gr][kp + cp];
                    a[i][1] = pA[rbase + gr + 8][kp + cp];
                    a[i][2] = pA[rbase + gr][kp + cp + 4];
                    a[i][3] = pA[rbase + gr + 8][kp + cp + 4];
                }
#pragma unroll
                for (int j = 0; j < 4; j++) {
                    int brow = wn0 + 8 * j + gr;
                    bf[j][0] = pB[brow][kp + cp];
                    bf[j][1] = pB[brow][kp + cp + 4];
                }
#pragma unroll
                for (int i = 0; i < 4; i++)
#pragma unroll
                    for (int j = 0; j < 4; j++)
                        mma16816(acc[i][j], a[i], bf[j]);
            }
        }
        __syncthreads();
    }
#pragma unroll
    for (int i = 0; i < 4; i++) {
#pragma unroll
        for (int j = 0; j < 4; j++) {
            int row = m0 + wm0 + 16 * i + gr;
            int col = n0 + wn0 + 8 * j + cp * 2;
            *(float2*)&C[(size_t)row * Nn + col] = make_float2(acc[i][j][0], acc[i][j][1]);
            *(float2*)&C[(size_t)(row + 8) * Nn + col] = make_float2(acc[i][j][2], acc[i][j][3]);
        }
    }
}

// ------------------------- x_proj with fused conv+silu (also writes xc) -----
__global__ __launch_bounds__(256) void k_xproj(
        const float* __restrict__ xproj_f, const float* __restrict__ xproj_b,
        const float* __restrict__ cwf, const float* __restrict__ cbf,
        const float* __restrict__ cwb, const float* __restrict__ cbb) {
    int m0 = blockIdx.x * 128;
    int dir = blockIdx.y;
    int b = m0 >> 13, s0 = m0 & (LL - 1);
    const float* xp = dir ? xproj_b : xproj_f;
    const float* cw = dir ? cwb : cwf;
    const float* cb = dir ? cbb : cbf;
    __shared__ float xcs[64][133];
    __shared__ float ws[64][41];
    int tid = threadIdx.x;
    int cc = tid & 63, seg = tid >> 6;
    int ty = tid >> 3, tx = tid & 7;
    float acc[4][5] = {};
    const float* xzb = g_xz + (size_t)b * LL * 512;
    float* gxc = g_xc[dir];

    for (int k0 = 0; k0 < 256; k0 += 64) {
        for (int i = tid; i < 64 * 40; i += 256) {
            int k = i / 40, n = i - k * 40;
            ws[k][n] = xp[n * 256 + k0 + k];
        }
        {
            int d = k0 + cc;
            float w0 = cw[d*4], w1 = cw[d*4+1], w2 = cw[d*4+2], w3 = cw[d*4+3];
            float bi = cb[d];
            int sbase = s0 + seg * 32;
            const float* xzd = xzb + d;
            float v1 = (sbase - 3 >= 0) ? xzd[(size_t)(dir ? (LL-1-(sbase-3)) : (sbase-3)) * 512] : 0.f;
            float v2 = (sbase - 2 >= 0) ? xzd[(size_t)(dir ? (LL-1-(sbase-2)) : (sbase-2)) * 512] : 0.f;
            float v3 = (sbase - 1 >= 0) ? xzd[(size_t)(dir ? (LL-1-(sbase-1)) : (sbase-1)) * 512] : 0.f;
#pragma unroll 4
            for (int j = 0; j < 32; j++) {
                int s = sbase + j;
                float v0 = v1; v1 = v2; v2 = v3;
                v3 = xzd[(size_t)(dir ? (LL-1-s) : s) * 512];
                float a = bi + w0*v0 + w1*v1 + w2*v2 + w3*v3;
                float xv = siluf(a);
                xcs[cc][seg * 32 + j] = xv;
                gxc[(size_t)(m0 + seg * 32 + j) * DI + d] = xv;
            }
        }
        __syncthreads();
#pragma unroll 8
        for (int k = 0; k < 64; k++) {
            float a0 = xcs[k][ty*4], a1 = xcs[k][ty*4+1], a2 = xcs[k][ty*4+2], a3 = xcs[k][ty*4+3];
            float bv[5];
#pragma unroll
            for (int j = 0; j < 5; j++) bv[j] = ws[k][tx*5 + j];
#pragma unroll
            for (int j = 0; j < 5; j++) {
                acc[0][j] = fmaf(a0, bv[j], acc[0][j]);
                acc[1][j] = fmaf(a1, bv[j], acc[1][j]);
                acc[2][j] = fmaf(a2, bv[j], acc[2][j]);
                acc[3][j] = fmaf(a3, bv[j], acc[3][j]);
            }
        }
        __syncthreads();
    }
    float* outp = g_dbl[dir];
#pragma unroll
    for (int i = 0; i < 4; i++)
#pragma unroll
        for (int j = 0; j < 5; j++)
            outp[(size_t)(m0 + ty * 4 + i) * NDBL + tx * 5 + j] = acc[i][j];
}

// ------------------------- dt kernel: {r = exp(-dt), cB = dt*xc} ------------
__global__ void k_dt(const float* __restrict__ dtw_f, const float* __restrict__ dtb_f,
                     const float* __restrict__ dtw_b, const float* __restrict__ dtb_b) {
    int dir = blockIdx.y;
    int m0 = blockIdx.x * 64;
    int d = threadIdx.x;
    const float* dtw = dir ? dtw_b : dtw_f;
    float dtb = (dir ? dtb_b : dtb_f)[d];
    float w[DTR];
#pragma unroll
    for (int i = 0; i < DTR; i++) w[i] = dtw[d * DTR + i];
    __shared__ float sr[64][8];
    const float* gsrc = g_dbl[dir];
    for (int i = threadIdx.x; i < 64 * 8; i += 256)
        sr[i >> 3][i & 7] = gsrc[(size_t)(m0 + (i >> 3)) * NDBL + (i & 7)];
    __syncthreads();
    const float* gxc = g_xc[dir];
    float2* out = g_rcb[dir];
#pragma unroll 2
    for (int t = 0; t < 64; t++) {
        float a = dtb;
#pragma unroll
        for (int i = 0; i < DTR; i++) a = fmaf(w[i], sr[t][i], a);
        float e = __expf(a);
        float r = __fdividef(1.f, 1.f + e);            // exp(-softplus(a))
        float dt;
        if (a > 15.f)       dt = a;
        else if (a > -3.f)  dt = __logf(1.f + e);
        else                dt = e * fmaf(e, fmaf(e, 0.33333334f, -0.5f), 1.f);
        float xv = gxc[(size_t)(m0 + t) * DI + d];
        out[(size_t)(m0 + t) * DI + d] = make_float2(r, dt * xv);
    }
}

// ------------------------- scan pass 1 --------------------------------------
__global__ void k_scan1(const float* __restrict__ Alog_f, const float* __restrict__ Alog_b) {
    int ch = blockIdx.x, b = blockIdx.y, dir = blockIdx.z, d = threadIdx.x;
    const float* Alog = dir ? Alog_b : Alog_f;
    __shared__ float sB[CHUNK][16];
    int t0 = ch * CHUNK;
    const float* gsrc = g_dbl[dir] + (size_t)(b * LL + t0) * NDBL;
    for (int i = threadIdx.x; i < CHUNK * 16; i += 256)
        sB[i >> 4][i & 15] = gsrc[(i >> 4) * NDBL + 8 + (i & 15)];
    float Ad[NS], h[NS];
    bool fast = true;
#pragma unroll
    for (int n = 0; n < NS; n++) {
        Ad[n] = -__expf(Alog[d * NS + n]);
        fast = fast && (fabsf(Ad[n] + (float)(n + 1)) <= 1e-5f * (n + 1));
    }
#pragma unroll
    for (int n = 0; n < NS; n++) h[n] = 0.f;
    const float2* rcb = g_rcb[dir] + (size_t)(b * LL + t0) * DI + d;
    float rP = 1.f, S = 0.f;
    __syncthreads();
    if (fast) {
#pragma unroll 2
        for (int t = 0; t < CHUNK; t++) {
            float2 rc = rcb[(size_t)t * DI];
            float wv[NS];
            mkpow(rc.x, wv);
            rP *= rc.x;
#pragma unroll
            for (int n = 0; n < NS; n++)
                h[n] = fmaf(wv[n], h[n], rc.y * sB[t][n]);
        }
    } else {
        for (int t = 0; t < CHUNK; t++) {
            float2 rc = rcb[(size_t)t * DI];
            float dt = -__logf(rc.x);
            S += dt;
#pragma unroll
            for (int n = 0; n < NS; n++)
                h[n] = fmaf(__expf(dt * Ad[n]), h[n], rc.y * sB[t][n]);
        }
    }
    int base = ((dir * NCH + ch) * BB + b) * NS;
    if (fast) {
        float pw[NS];
        mkpow(rP, pw);
#pragma unroll
        for (int n = 0; n < NS; n++) {
            g_hend[(base + n) * DI + d] = h[n];
            g_P[(base + n) * DI + d]    = pw[n];
        }
    } else {
#pragma unroll
        for (int n = 0; n < NS; n++) {
            g_hend[(base + n) * DI + d] = h[n];
            g_P[(base + n) * DI + d]    = __expf(Ad[n] * S);
        }
    }
}

// ------------------------- scan pass 2 --------------------------------------
__global__ void k_scan2() {
    int d = threadIdx.x;
    int n   = blockIdx.x & 15;
    int b   = (blockIdx.x >> 4) & 3;
    int dir = blockIdx.x >> 6;
    float hs = 0.f;
    for (int ch = 0; ch < NCH; ch++) {
        int idx = (((dir * NCH + ch) * BB + b) * NS + n) * DI + d;
        g_hinit[idx] = hs;
        hs = fmaf(g_P[idx], hs, g_hend[idx]);
    }
}

// ------------------------- scan pass 3 --------------------------------------
__global__ void k_scan3(const float* __restrict__ Alog_f, const float* __restrict__ Dsk_f,
                        const float* __restrict__ Alog_b, const float* __restrict__ Dsk_b) {
    int ch = blockIdx.x, b = blockIdx.y, dir = blockIdx.z, d = threadIdx.x;
    const float* Alog = dir ? Alog_b : Alog_f;
    float Dd = (dir ? Dsk_b : Dsk_f)[d];
    __shared__ float sBC[CHUNK][32];
    int t0 = ch * CHUNK;
    const float* gsrc = g_dbl[dir] + (size_t)(b * LL + t0) * NDBL;
    for (int i = threadIdx.x; i < CHUNK * 32; i += 256)
        sBC[i >> 5][i & 31] = gsrc[(i >> 5) * NDBL + 8 + (i & 31)];
    float Ad[NS], h[NS];
    bool fast = true;
#pragma unroll
    for (int n = 0; n < NS; n++) {
        Ad[n] = -__expf(Alog[d * NS + n]);
        fast = fast && (fabsf(Ad[n] + (float)(n + 1)) <= 1e-5f * (n + 1));
    }
    int base = ((dir * NCH + ch) * BB + b) * NS;
#pragma unroll
    for (int n = 0; n < NS; n++) h[n] = g_hinit[(base + n) * DI + d];
    const float2* rcb = g_rcb[dir] + (size_t)(b * LL + t0) * DI + d;
    const float*  gxc = g_xc[dir]  + (size_t)(b * LL + t0) * DI + d;
    const float*  xzz = g_xz + (size_t)b * LL * 512 + DI + d;
    float* yout = g_ydir[dir] + (size_t)b * LL * DI + d;
    __syncthreads();
    if (fast) {
#pragma unroll 2
        for (int t = 0; t < CHUNK; t++) {
            float2 rc = rcb[(size_t)t * DI];
            float xv = gxc[(size_t)t * DI];
            float wv[NS];
            mkpow(rc.x, wv);
            float y = 0.f;
#pragma unroll
            for (int n = 0; n < NS; n++) {
                h[n] = fmaf(wv[n], h[n], rc.y * sBC[t][n]);
                y = fmaf(h[n], sBC[t][16 + n], y);
            }
            int torig = dir ? (LL - 1 - (t0 + t)) : (t0 + t);
            float zv = xzz[(size_t)torig * 512];
            yout[(size_t)torig * DI] = (y + xv * Dd) * siluf(zv);
        }
    } else {
        for (int t = 0; t < CHUNK; t++) {
            float2 rc = rcb[(size_t)t * DI];
            float xv = gxc[(size_t)t * DI];
            float dt = -__logf(rc.x);
            float y = 0.f;
#pragma unroll
            for (int n = 0; n < NS; n++) {
                h[n] = fmaf(__expf(dt * Ad[n]), h[n], rc.y * sBC[t][n]);
                y = fmaf(h[n], sBC[t][16 + n], y);
            }
            int torig = dir ? (LL - 1 - (t0 + t)) : (t0 + t);
            float zv = xzz[(size_t)torig * 512];
            yout[(size_t)torig * DI] = (y + xv * Dd) * siluf(zv);
        }
    }
}

// ------------------------- sum + bf16 split for out_proj --------------------
__global__ void k_sumconv() {
    size_t i = (size_t)blockIdx.x * 256 + threadIdx.x;
    float v = g_ydir[0][i] + g_ydir[1][i];
    bsplit(v, g_yh[i], g_yl[i]);
}

// ------------------------- LN2 + residual + transpose back ------------------
__global__ void k_ln2(const float* __restrict__ w, const float* __restrict__ bia,
                      float* __restrict__ out) {
    __shared__ float s[DM][65];
    __shared__ float rs_[4][64], rq_[4][64];
    __shared__ float mu[64], rstd[64];
    int tid = threadIdx.x;
    int m0 = blockIdx.x * 64;
    int b  = m0 / LL;
    int l0 = m0 % LL;
#pragma unroll
    for (int i = 0; i < 32; i++) {
        int e = tid + i * 256;
        int c = e & 127, l = e >> 7;
        int gi = (m0 + l) * DM + c;
        s[c][l] = g_outpre[gi] + g_xflat[gi];
    }
    __syncthreads();
    {
        int tok = tid & 63, part = tid >> 6;
        float su = 0.f, sq = 0.f;
#pragma unroll
        for (int cc = 0; cc < 32; cc++) {
            float v = s[part * 32 + cc][tok];
            su += v; sq = fmaf(v, v, sq);
        }
        rs_[part][tok] = su; rq_[part][tok] = sq;
    }
    __syncthreads();
    if (tid < 64) {
        float su = rs_[0][tid] + rs_[1][tid] + rs_[2][tid] + rs_[3][tid];
        float sq = rq_[0][tid] + rq_[1][tid] + rq_[2][tid] + rq_[3][tid];
        float m = su * (1.f / DM);
        float var = sq * (1.f / DM) - m * m;
        mu[tid] = m; rstd[tid] = rsqrtf(var + 1e-5f);
    }
    __syncthreads();
#pragma unroll
    for (int i = 0; i < 32; i++) {
        int e = tid + i * 256;
        int l = e & 63, c = e >> 6;
        out[(b * DM + c) * LL + l0 + l] = (s[c][l] - mu[l]) * rstd[l] * w[c] + bia[c];
    }
}

// ------------------------- launch ------------------------------------------
extern "C" void kernel_launch(void* const* d_in, const int* in_sizes, int n_in,
                              void* d_out, int out_size) {
    const float* x        = (const float*)d_in[0];
    const float* ln1_w    = (const float*)d_in[1];
    const float* ln1_b    = (const float*)d_in[2];
    const float* ln2_w    = (const float*)d_in[3];
    const float* ln2_b    = (const float*)d_in[4];
    const float* in_proj  = (const float*)d_in[5];
    const float* out_proj = (const float*)d_in[6];
    const float* conv_w_f = (const float*)d_in[7];
    const float* conv_b_f = (const float*)d_in[8];
    const float* xproj_f  = (const float*)d_in[9];
    const float* dtw_f    = (const float*)d_in[10];
    const float* dtb_f    = (const float*)d_in[11];
    const float* Alog_f   = (const float*)d_in[12];
    const float* D_f      = (const float*)d_in[13];
    const float* conv_w_b = (const float*)d_in[14];
    const float* conv_b_b = (const float*)d_in[15];
    const float* xproj_b  = (const float*)d_in[16];
    const float* dtw_b    = (const float*)d_in[17];
    const float* dtb_b    = (const float*)d_in[18];
    const float* Alog_b   = (const float*)d_in[19];
    const float* D_b      = (const float*)d_in[20];
    float* out = (float*)d_out;

    float *p_xz, *p_outpre;
    __nv_bfloat16 *p_xnh, *p_xnl, *p_yh, *p_yl, *p_wih, *p_wil, *p_woh, *p_wol;
    cudaGetSymbolAddress((void**)&p_xz,     g_xz);
    cudaGetSymbolAddress((void**)&p_outpre, g_outpre);
    cudaGetSymbolAddress((void**)&p_xnh,    g_xnh);
    cudaGetSymbolAddress((void**)&p_xnl,    g_xnl);
    cudaGetSymbolAddress((void**)&p_yh,     g_yh);
    cudaGetSymbolAddress((void**)&p_yl,     g_yl);
    cudaGetSymbolAddress((void**)&p_wih,    g_wih);
    cudaGetSymbolAddress((void**)&p_wil,    g_wil);
    cudaGetSymbolAddress((void**)&p_woh,    g_woh);
    cudaGetSymbolAddress((void**)&p_wol,    g_wol);

    // 0. weight bf16 split
    k_wconv<<<(512 * 128 + 128 * 256 + 255) / 256, 256>>>(in_proj, out_proj);

    // 1. LN1 + transpose + split
    k_ln1<<<MTOK / 64, 256>>>(x, ln1_w, ln1_b);

    // 2. in_proj on tensor cores: [32768,128] x [512,128]^T -> g_xz
    gemm_mma<DM><<<dim3(MTOK / 128, 4), 256>>>(p_xnh, p_xnl, p_wih, p_wil, p_xz, 2 * DI);

    // 3. x_proj (conv+silu fused, persists xc)
    k_xproj<<<dim3(MTOK / 128, 2), 256>>>(xproj_f, xproj_b,
                                          conv_w_f, conv_b_f, conv_w_b, conv_b_b);

    // 4. dt precompute -> {r, cB}
    k_dt<<<dim3(MTOK / 64, 2), 256>>>(dtw_f, dtb_f, dtw_b, dtb_b);

    // 5-7. chunked selective scan (MUFU-free hot loops)
    k_scan1<<<dim3(NCH, BB, 2), 256>>>(Alog_f, Alog_b);
    k_scan2<<<2 * BB * NS, 256>>>();
    k_scan3<<<dim3(NCH, BB, 2), 256>>>(Alog_f, D_f, Alog_b, D_b);

    // 8. y_f + y_b -> bf16 split
    k_sumconv<<<MTOK * DI / 256, 256>>>();

    // 9. out_proj on tensor cores: [32768,256] x [128,256]^T -> g_outpre
    gemm_mma<DI><<<dim3(MTOK / 128, 1), 256>>>(p_yh, p_yl, p_woh, p_wol, p_outpre, DM);

    // 10. residual + LN2 + transpose back
    k_ln2<<<MTOK / 64, 256>>>(ln2_w, ln2_b, out);
}

// round 7
// speedup vs baseline: 1.3239x; 1.0422x over previous
#include <cuda_runtime.h>
#include <cuda_bf16.h>
#include <cstdint>

// ---------------------------------------------------------------------------
// MambaLayer (bidirectional VideoMamba), B200 sm_100 — round 7
// all GEMMs on mma.sync (bf16-split); conv fused once; vectorized scans
// ---------------------------------------------------------------------------

#define BB   4
#define DM   128
#define LL   8192
#define DI   256
#define NS   16
#define DTR  8
#define NDBL 40
#define MTOK (BB*LL)
#define CHUNK 64
#define NCH  (LL/CHUNK)

// ------------------------- scratch (static device mem) ---------------------
__device__ float          g_xflat [MTOK*DM];
__device__ __nv_bfloat16  g_xnh   [MTOK*DM];
__device__ __nv_bfloat16  g_xnl   [MTOK*DM];
__device__ float          g_xz    [MTOK*2*DI];
__device__ float          g_dbl   [2][MTOK*NDBL];
__device__ __nv_bfloat16  g_xch   [2][MTOK*DI];
__device__ __nv_bfloat16  g_xcl   [2][MTOK*DI];
__device__ float2         g_rcb   [2][MTOK*DI];
__device__ float          g_ydir  [2][MTOK*DI];
__device__ float          g_hend  [2*NCH*BB*NS*DI];
__device__ float          g_P     [2*NCH*BB*NS*DI];
__device__ float          g_hinit [2*NCH*BB*NS*DI];
__device__ float          g_outpre[MTOK*DM];
__device__ __nv_bfloat16  g_wih[512*128],  g_wil[512*128];
__device__ __nv_bfloat16  g_woh[128*256],  g_wol[128*256];
__device__ __nv_bfloat16  g_xpwh[2][128*256], g_xpwl[2][128*256]; // rows>=40 zero

// ------------------------- math helpers -------------------------------------
__device__ __forceinline__ float siluf(float x) {
    return __fdividef(x, 1.f + __expf(-x));
}
__device__ __forceinline__ void mkpow(float r, float* w) {
    float r2 = r * r, r3 = r2 * r, r4 = r2 * r2;
    float r5 = r4 * r, r6 = r4 * r2, r7 = r4 * r3, r8 = r4 * r4;
    w[0]=r;  w[1]=r2; w[2]=r3; w[3]=r4; w[4]=r5; w[5]=r6; w[6]=r7; w[7]=r8;
    w[8]=r8*r; w[9]=r8*r2; w[10]=r8*r3; w[11]=r8*r4;
    w[12]=r8*r5; w[13]=r8*r6; w[14]=r8*r7; w[15]=r8*r8;
}
__device__ __forceinline__ void bsplit(float v, __nv_bfloat16& hi, __nv_bfloat16& lo) {
    hi = __float2bfloat16(v);
    lo = __float2bfloat16(v - __bfloat162float(hi));
}
__device__ __forceinline__ uint32_t pack2(__nv_bfloat16 a, __nv_bfloat16 b) {
    return (uint32_t)__bfloat16_as_ushort(a) | ((uint32_t)__bfloat16_as_ushort(b) << 16);
}

// ------------------------- weight convert -----------------------------------
__global__ void k_wconv(const float* __restrict__ wi, const float* __restrict__ wo,
                        const float* __restrict__ xpf, const float* __restrict__ xpb) {
    int i = blockIdx.x * 256 + threadIdx.x;
    if (i < 512 * 128) { bsplit(wi[i], g_wih[i], g_wil[i]); return; }
    int j = i - 512 * 128;
    if (j < 128 * 256) { bsplit(wo[j], g_woh[j], g_wol[j]); return; }
    int k = j - 128 * 256;
    if (k < 2 * NDBL * 256) {
        int dir = k / (NDBL * 256);
        int idx = k - dir * NDBL * 256;          // n*256 + c, n < 40
        const float* src = dir ? xpb : xpf;
        bsplit(src[idx], g_xpwh[dir][idx], g_xpwl[dir][idx]);
    }
}

// ------------------------- LN1 + transpose + bf16 split ---------------------
__global__ void k_ln1(const float* __restrict__ x,
                      const float* __restrict__ w, const float* __restrict__ bia) {
    __shared__ float s[DM][65];
    __shared__ float rs_[4][64], rq_[4][64];
    __shared__ float mu[64], rstd[64];
    int tid = threadIdx.x;
    int m0 = blockIdx.x * 64;
    int b  = m0 / LL;
    int l0 = m0 % LL;
#pragma unroll
    for (int i = 0; i < 32; i++) {
        int e = tid + i * 256;
        int l = e & 63, c = e >> 6;
        s[c][l] = x[(b * DM + c) * LL + l0 + l];
    }
    __syncthreads();
    {
        int tok = tid & 63, part = tid >> 6;
        float su = 0.f, sq = 0.f;
#pragma unroll
        for (int cc = 0; cc < 32; cc++) {
            float v = s[part * 32 + cc][tok];
            su += v; sq = fmaf(v, v, sq);
        }
        rs_[part][tok] = su; rq_[part][tok] = sq;
    }
    __syncthreads();
    if (tid < 64) {
        float su = rs_[0][tid] + rs_[1][tid] + rs_[2][tid] + rs_[3][tid];
        float sq = rq_[0][tid] + rq_[1][tid] + rq_[2][tid] + rq_[3][tid];
        float m = su * (1.f / DM);
        float var = sq * (1.f / DM) - m * m;
        mu[tid] = m; rstd[tid] = rsqrtf(var + 1e-5f);
    }
    __syncthreads();
#pragma unroll
    for (int i = 0; i < 32; i++) {
        int e = tid + i * 256;
        int c = e & 127, l = e >> 7;
        float v = s[c][l];
        int gi = (m0 + l) * DM + c;
        g_xflat[gi] = v;
        float vn = (v - mu[l]) * rstd[l] * w[c] + bia[c];
        bsplit(vn, g_xnh[gi], g_xnl[gi]);
    }
}

// ------------------------- mma.sync bf16-split GEMM -------------------------
// C[m][n] = A[m][K] . B[n][K]^T via AhBh + AhBl + AlBh.
// SUMA=false: A1/A2 are bf16 hi/lo.  SUMA=true: A1/A2 are float, A=A1+A2 (split inline).
__device__ __forceinline__ void mma16816(float* c, const uint32_t* a, const uint32_t* b) {
    asm volatile(
        "mma.sync.aligned.m16n8k16.row.col.f32.bf16.bf16.f32 "
        "{%0,%1,%2,%3}, {%4,%5,%6,%7}, {%8,%9}, {%0,%1,%2,%3};"
        : "+f"(c[0]), "+f"(c[1]), "+f"(c[2]), "+f"(c[3])
        : "r"(a[0]), "r"(a[1]), "r"(a[2]), "r"(a[3]), "r"(b[0]), "r"(b[1]));
}

template<int KTOT, bool SUMA>
__global__ __launch_bounds__(256) void gemm_mma(
        const void* __restrict__ A1, const void* __restrict__ A2,
        const __nv_bfloat16* __restrict__ Bh, const __nv_bfloat16* __restrict__ Bl,
        float* __restrict__ C, int Nn) {
    __shared__ uint32_t As[2][128][18];
    __shared__ uint32_t Bs[2][128][18];
    const int tid = threadIdx.x;
    const int m0 = blockIdx.x * 128, n0 = blockIdx.y * 128;
    const int wid = tid >> 5, lane = tid & 31;
    const int wm0 = (wid & 1) * 64, wn0 = (wid >> 1) * 32;
    const int gr = lane >> 2, cp = lane & 3;
    float acc[4][4][4] = {};

    const int lrow = tid >> 1, lhalf = tid & 1;
    for (int k0 = 0; k0 < KTOT; k0 += 32) {
        // ---- stage A (hi/lo) ----
        if (SUMA) {
            const float* Yf = (const float*)A1;
            const float* Yb = (const float*)A2;
            const float4* pf = (const float4*)&Yf[(size_t)(m0 + lrow) * KTOT + k0 + lhalf * 16];
            const float4* pb = (const float4*)&Yb[(size_t)(m0 + lrow) * KTOT + k0 + lhalf * 16];
            float v[16];
#pragma unroll
            for (int q = 0; q < 4; q++) {
                float4 a = pf[q], bq = pb[q];
                v[q*4+0] = a.x + bq.x; v[q*4+1] = a.y + bq.y;
                v[q*4+2] = a.z + bq.z; v[q*4+3] = a.w + bq.w;
            }
            uint32_t* dh = &As[0][lrow][lhalf * 8];
            uint32_t* dl = &As[1][lrow][lhalf * 8];
#pragma unroll
            for (int q = 0; q < 8; q++) {
                __nv_bfloat16 h0, l0, h1, l1;
                bsplit(v[2*q], h0, l0);
                bsplit(v[2*q+1], h1, l1);
                dh[q] = pack2(h0, h1);
                dl[q] = pack2(l0, l1);
            }
        } else {
#pragma unroll
            for (int sel = 0; sel < 2; sel++) {
                const __nv_bfloat16* src = sel ? (const __nv_bfloat16*)A2
                                               : (const __nv_bfloat16*)A1;
                const uint4* gp = (const uint4*)&src[(size_t)(m0 + lrow) * KTOT + k0 + lhalf * 16];
                uint4 v0 = gp[0], v1 = gp[1];
                uint32_t* d = &As[sel][lrow][lhalf * 8];
                d[0] = v0.x; d[1] = v0.y; d[2] = v0.z; d[3] = v0.w;
                d[4] = v1.x; d[5] = v1.y; d[6] = v1.z; d[7] = v1.w;
            }
        }
        // ---- stage B (hi/lo) ----
#pragma unroll
        for (int sel = 0; sel < 2; sel++) {
            const __nv_bfloat16* src = sel ? Bl : Bh;
            const uint4* gp = (const uint4*)&src[(size_t)(n0 + lrow) * KTOT + k0 + lhalf * 16];
            uint4 v0 = gp[0], v1 = gp[1];
            uint32_t* d = &Bs[sel][lrow][lhalf * 8];
            d[0] = v0.x; d[1] = v0.y; d[2] = v0.z; d[3] = v0.w;
            d[4] = v1.x; d[5] = v1.y; d[6] = v1.z; d[7] = v1.w;
        }
        __syncthreads();
#pragma unroll
        for (int pass = 0; pass < 3; pass++) {
            uint32_t (*pA)[18] = As[pass == 2 ? 1 : 0];
            uint32_t (*pB)[18] = Bs[pass == 1 ? 1 : 0];
#pragma unroll
            for (int k16 = 0; k16 < 2; k16++) {
                const int kp = k16 * 8;
                uint32_t a[4][4], bf[4][2];
#pragma unroll
                for (int i = 0; i < 4; i++) {
                    int rbase = wm0 + 16 * i;
                    a[i][0] = pA[rbase + gr][kp + cp];
                    a[i][1] = pA[rbase + gr + 8][kp + cp];
                    a[i][2] = pA[rbase + gr][kp + cp + 4];
                    a[i][3] = pA[rbase + gr + 8][kp + cp + 4];
                }
#pragma unroll
                for (int j = 0; j < 4; j++) {
                    int brow = wn0 + 8 * j + gr;
                    bf[j][0] = pB[brow][kp + cp];
                    bf[j][1] = pB[brow][kp + cp + 4];
                }
#pragma unroll
                for (int i = 0; i < 4; i++)
#pragma unroll
                    for (int j = 0; j < 4; j++)
                        mma16816(acc[i][j], a[i], bf[j]);
            }
        }
        __syncthreads();
    }
#pragma unroll
    for (int i = 0; i < 4; i++) {
#pragma unroll
        for (int j = 0; j < 4; j++) {
            int row = m0 + wm0 + 16 * i + gr;
            int col = n0 + wn0 + 8 * j + cp * 2;
            if (col < Nn) {
                *(float2*)&C[(size_t)row * Nn + col] = make_float2(acc[i][j][0], acc[i][j][1]);
                *(float2*)&C[(size_t)(row + 8) * Nn + col] = make_float2(acc[i][j][2], acc[i][j][3]);
            }
        }
    }
}

// ------------------------- conv + silu + bf16 split, BOTH dirs --------------
// fwd[t] = silu(conv_f(x)[t]); bwd seq-pos s=LL-1-t uses taps x[t..t+3]
__global__ void k_conv2(const float* __restrict__ cwf, const float* __restrict__ cbf,
                        const float* __restrict__ cwb, const float* __restrict__ cbb) {
    int d = threadIdx.x;
    int t0 = blockIdx.x * 64;
    int b = blockIdx.y;
    float wf0 = cwf[d*4], wf1 = cwf[d*4+1], wf2 = cwf[d*4+2], wf3 = cwf[d*4+3];
    float bf = cbf[d];
    float wb0 = cwb[d*4], wb1 = cwb[d*4+1], wb2 = cwb[d*4+2], wb3 = cwb[d*4+3];
    float bb = cbb[d];
    const float* xp = g_xz + (size_t)(b * LL) * 512 + d;
    float v[7];
#pragma unroll
    for (int j = 0; j < 7; j++) {
        int tt = t0 - 3 + j;
        v[j] = (tt >= 0 && tt < LL) ? xp[(size_t)tt * 512] : 0.f;
    }
#pragma unroll 4
    for (int i = 0; i < 64; i++) {
        int t = t0 + i;
        float f  = bf + wf0*v[0] + wf1*v[1] + wf2*v[2] + wf3*v[3];
        float bw = bb + wb0*v[6] + wb1*v[5] + wb2*v[4] + wb3*v[3];
        float xf = siluf(f), xb = siluf(bw);
        size_t rf = (size_t)(b * LL + t) * DI + d;
        size_t rb = (size_t)(b * LL + (LL - 1 - t)) * DI + d;
        __nv_bfloat16 h, l;
        bsplit(xf, h, l); g_xch[0][rf] = h; g_xcl[0][rf] = l;
        bsplit(xb, h, l); g_xch[1][rb] = h; g_xcl[1][rb] = l;
        v[0]=v[1]; v[1]=v[2]; v[2]=v[3]; v[3]=v[4]; v[4]=v[5]; v[5]=v[6];
        int tn = t + 4;
        v[6] = (tn < LL) ? xp[(size_t)tn * 512] : 0.f;
    }
}

// ------------------------- dt kernel: {r = exp(-dt), cB = dt*xc} ------------
__global__ void k_dt(const float* __restrict__ dtw_f, const float* __restrict__ dtb_f,
                     const float* __restrict__ dtw_b, const float* __restrict__ dtb_b) {
    int dir = blockIdx.y;
    int m0 = blockIdx.x * 64;
    int d = threadIdx.x;
    const float* dtw = dir ? dtw_b : dtw_f;
    float dtb = (dir ? dtb_b : dtb_f)[d];
    float w[DTR];
#pragma unroll
    for (int i = 0; i < DTR; i++) w[i] = dtw[d * DTR + i];
    __shared__ __align__(16) float sr[64][8];
    const float* gsrc = g_dbl[dir];
    if (threadIdx.x < 128) {
        int t = threadIdx.x >> 1, q = threadIdx.x & 1;
        *((float4*)&sr[t][q * 4]) = *((const float4*)&gsrc[(size_t)(m0 + t) * NDBL + q * 4]);
    }
    __syncthreads();
    const __nv_bfloat16* xh = g_xch[dir] + (size_t)m0 * DI + d;
    const __nv_bfloat16* xl = g_xcl[dir] + (size_t)m0 * DI + d;
    float2* out = g_rcb[dir];
#pragma unroll 2
    for (int t = 0; t < 64; t++) {
        float4 r0 = *((const float4*)&sr[t][0]);
        float4 r1 = *((const float4*)&sr[t][4]);
        float a = dtb;
        a = fmaf(w[0], r0.x, a); a = fmaf(w[1], r0.y, a);
        a = fmaf(w[2], r0.z, a); a = fmaf(w[3], r0.w, a);
        a = fmaf(w[4], r1.x, a); a = fmaf(w[5], r1.y, a);
        a = fmaf(w[6], r1.z, a); a = fmaf(w[7], r1.w, a);
        float e = __expf(a);
        float r = __fdividef(1.f, 1.f + e);            // exp(-softplus(a))
        float dt;
        if (a > 15.f)       dt = a;
        else if (a > -3.f)  dt = __logf(1.f + e);
        else                dt = e * fmaf(e, fmaf(e, 0.33333334f, -0.5f), 1.f);
        float xv = __bfloat162float(xh[(size_t)t * DI]) + __bfloat162float(xl[(size_t)t * DI]);
        out[(size_t)(m0 + t) * DI + d] = make_float2(r, dt * xv);
    }
}

// ------------------------- scan pass 1 --------------------------------------
__global__ void k_scan1(const float* __restrict__ Alog_f, const float* __restrict__ Alog_b) {
    int ch = blockIdx.x, b = blockIdx.y, dir = blockIdx.z, d = threadIdx.x;
    const float* Alog = dir ? Alog_b : Alog_f;
    __shared__ __align__(16) float sB[CHUNK][16];
    int t0 = ch * CHUNK;
    const float* gsrc = g_dbl[dir] + (size_t)(b * LL + t0) * NDBL;
    for (int i = threadIdx.x; i < CHUNK * 4; i += 256) {
        int t = i >> 2, q = i & 3;
        *((float4*)&sB[t][q * 4]) = *((const float4*)&gsrc[t * NDBL + 8 + q * 4]);
    }
    float Ad[NS], h[NS];
    bool fast = true;
#pragma unroll
    for (int n = 0; n < NS; n++) {
        Ad[n] = -__expf(Alog[d * NS + n]);
        fast = fast && (fabsf(Ad[n] + (float)(n + 1)) <= 1e-5f * (n + 1));
    }
#pragma unroll
    for (int n = 0; n < NS; n++) h[n] = 0.f;
    const float2* rcb = g_rcb[dir] + (size_t)(b * LL + t0) * DI + d;
    float rP = 1.f, S = 0.f;
    __syncthreads();
    if (fast) {
#pragma unroll 2
        for (int t = 0; t < CHUNK; t++) {
            float2 rc = rcb[(size_t)t * DI];
            const float4* pb = (const float4*)sB[t];
            float4 B0 = pb[0], B1 = pb[1], B2 = pb[2], B3 = pb[3];
            float Bv[16] = {B0.x,B0.y,B0.z,B0.w, B1.x,B1.y,B1.z,B1.w,
                            B2.x,B2.y,B2.z,B2.w, B3.x,B3.y,B3.z,B3.w};
            float wv[NS];
            mkpow(rc.x, wv);
            rP *= rc.x;
#pragma unroll
            for (int n = 0; n < NS; n++)
                h[n] = fmaf(wv[n], h[n], rc.y * Bv[n]);
        }
    } else {
        for (int t = 0; t < CHUNK; t++) {
            float2 rc = rcb[(size_t)t * DI];
            float dt = -__logf(rc.x);
            S += dt;
#pragma unroll
            for (int n = 0; n < NS; n++)
                h[n] = fmaf(__expf(dt * Ad[n]), h[n], rc.y * sB[t][n]);
        }
    }
    int base = ((dir * NCH + ch) * BB + b) * NS;
    if (fast) {
        float pw[NS];
        mkpow(rP, pw);
#pragma unroll
        for (int n = 0; n < NS; n++) {
            g_hend[(base + n) * DI + d] = h[n];
            g_P[(base + n) * DI + d]    = pw[n];
        }
    } else {
#pragma unroll
        for (int n = 0; n < NS; n++) {
            g_hend[(base + n) * DI + d] = h[n];
            g_P[(base + n) * DI + d]    = __expf(Ad[n] * S);
        }
    }
}

// ------------------------- scan pass 2 --------------------------------------
__global__ void k_scan2() {
    int d = threadIdx.x;
    int n   = blockIdx.x & 15;
    int b   = (blockIdx.x >> 4) & 3;
    int dir = blockIdx.x >> 6;
    float hs = 0.f;
    for (int ch = 0; ch < NCH; ch++) {
        int idx = (((dir * NCH + ch) * BB + b) * NS + n) * DI + d;
        g_hinit[idx] = hs;
        hs = fmaf(g_P[idx], hs, g_hend[idx]);
    }
}

// ------------------------- scan pass 3 --------------------------------------
__global__ void k_scan3(const float* __restrict__ Alog_f, const float* __restrict__ Dsk_f,
                        const float* __restrict__ Alog_b, const float* __restrict__ Dsk_b) {
    int ch = blockIdx.x, b = blockIdx.y, dir = blockIdx.z, d = threadIdx.x;
    const float* Alog = dir ? Alog_b : Alog_f;
    float Dd = (dir ? Dsk_b : Dsk_f)[d];
    __shared__ __align__(16) float sBC[CHUNK][32];
    int t0 = ch * CHUNK;
    const float* gsrc = g_dbl[dir] + (size_t)(b * LL + t0) * NDBL;
    for (int i = threadIdx.x; i < CHUNK * 8; i += 256) {
        int t = i >> 3, q = i & 7;
        *((float4*)&sBC[t][q * 4]) = *((const float4*)&gsrc[t * NDBL + 8 + q * 4]);
    }
    float Ad[NS], h[NS];
    bool fast = true;
#pragma unroll
    for (int n = 0; n < NS; n++) {
        Ad[n] = -__expf(Alog[d * NS + n]);
        fast = fast && (fabsf(Ad[n] + (float)(n + 1)) <= 1e-5f * (n + 1));
    }
    int base = ((dir * NCH + ch) * BB + b) * NS;
#pragma unroll
    for (int n = 0; n < NS; n++) h[n] = g_hinit[(base + n) * DI + d];
    const float2* rcb = g_rcb[dir] + (size_t)(b * LL + t0) * DI + d;
    const __nv_bfloat16* xh = g_xch[dir] + (size_t)(b * LL + t0) * DI + d;
    const __nv_bfloat16* xl = g_xcl[dir] + (size_t)(b * LL + t0) * DI + d;
    const float* xzz = g_xz + (size_t)b * LL * 512 + DI + d;
    float* yout = g_ydir[dir] + (size_t)b * LL * DI + d;
    __syncthreads();
    if (fast) {
#pragma unroll 2
        for (int t = 0; t < CHUNK; t++) {
            float2 rc = rcb[(size_t)t * DI];
            float xv = __bfloat162float(xh[(size_t)t * DI]) + __bfloat162float(xl[(size_t)t * DI]);
            const float4* pr = (const float4*)sBC[t];
            float4 B0 = pr[0], B1 = pr[1], B2 = pr[2], B3 = pr[3];
            float4 C0 = pr[4], C1 = pr[5], C2 = pr[6], C3 = pr[7];
            float Bv[16] = {B0.x,B0.y,B0.z,B0.w, B1.x,B1.y,B1.z,B1.w,
                            B2.x,B2.y,B2.z,B2.w, B3.x,B3.y,B3.z,B3.w};
            float Cv[16] = {C0.x,C0.y,C0.z,C0.w, C1.x,C1.y,C1.z,C1.w,
                            C2.x,C2.y,C2.z,C2.w, C3.x,C3.y,C3.z,C3.w};
            float wv[NS];
            mkpow(rc.x, wv);
            float y = 0.f;
#pragma unroll
            for (int n = 0; n < NS; n++) {
                h[n] = fmaf(wv[n], h[n], rc.y * Bv[n]);
                y = fmaf(h[n], Cv[n], y);
            }
            int torig = dir ? (LL - 1 - (t0 + t)) : (t0 + t);
            float zv = xzz[(size_t)torig * 512];
            yout[(size_t)torig * DI] = (y + xv * Dd) * siluf(zv);
        }
    } else {
        for (int t = 0; t < CHUNK; t++) {
            float2 rc = rcb[(size_t)t * DI];
            float xv = __bfloat162float(xh[(size_t)t * DI]) + __bfloat162float(xl[(size_t)t * DI]);
            float dt = -__logf(rc.x);
            float y = 0.f;
#pragma unroll
            for (int n = 0; n < NS; n++) {
                h[n] = fmaf(__expf(dt * Ad[n]), h[n], rc.y * sBC[t][n]);
                y = fmaf(h[n], sBC[t][16 + n], y);
            }
            int torig = dir ? (LL - 1 - (t0 + t)) : (t0 + t);
            float zv = xzz[(size_t)torig * 512];
            yout[(size_t)torig * DI] = (y + xv * Dd) * siluf(zv);
        }
    }
}

// ------------------------- LN2 + residual + transpose back ------------------
__global__ void k_ln2(const float* __restrict__ w, const float* __restrict__ bia,
                      float* __restrict__ out) {
    __shared__ float s[DM][65];
    __shared__ float rs_[4][64], rq_[4][64];
    __shared__ float mu[64], rstd[64];
    int tid = threadIdx.x;
    int m0 = blockIdx.x * 64;
    int b  = m0 / LL;
    int l0 = m0 % LL;
#pragma unroll
    for (int i = 0; i < 32; i++) {
        int e = tid + i * 256;
        int c = e & 127, l = e >> 7;
        int gi = (m0 + l) * DM + c;
        s[c][l] = g_outpre[gi] + g_xflat[gi];
    }
    __syncthreads();
    {
        int tok = tid & 63, part = tid >> 6;
        float su = 0.f, sq = 0.f;
#pragma unroll
        for (int cc = 0; cc < 32; cc++) {
            float v = s[part * 32 + cc][tok];
            su += v; sq = fmaf(v, v, sq);
        }
        rs_[part][tok] = su; rq_[part][tok] = sq;
    }
    __syncthreads();
    if (tid < 64) {
        float su = rs_[0][tid] + rs_[1][tid] + rs_[2][tid] + rs_[3][tid];
        float sq = rq_[0][tid] + rq_[1][tid] + rq_[2][tid] + rq_[3][tid];
        float m = su * (1.f / DM);
        float var = sq * (1.f / DM) - m * m;
        mu[tid] = m; rstd[tid] = rsqrtf(var + 1e-5f);
    }
    __syncthreads();
#pragma unroll
    for (int i = 0; i < 32; i++) {
        int e = tid + i * 256;
        int l = e & 63, c = e >> 6;
        out[(b * DM + c) * LL + l0 + l] = (s[c][l] - mu[l]) * rstd[l] * w[c] + bia[c];
    }
}

// ------------------------- launch ------------------------------------------
extern "C" void kernel_launch(void* const* d_in, const int* in_sizes, int n_in,
                              void* d_out, int out_size) {
    const float* x        = (const float*)d_in[0];
    const float* ln1_w    = (const float*)d_in[1];
    const float* ln1_b    = (const float*)d_in[2];
    const float* ln2_w    = (const float*)d_in[3];
    const float* ln2_b    = (const float*)d_in[4];
    const float* in_proj  = (const float*)d_in[5];
    const float* out_proj = (const float*)d_in[6];
    const float* conv_w_f = (const float*)d_in[7];
    const float* conv_b_f = (const float*)d_in[8];
    const float* xproj_f  = (const float*)d_in[9];
    const float* dtw_f    = (const float*)d_in[10];
    const float* dtb_f    = (const float*)d_in[11];
    const float* Alog_f   = (const float*)d_in[12];
    const float* D_f      = (const float*)d_in[13];
    const float* conv_w_b = (const float*)d_in[14];
    const float* conv_b_b = (const float*)d_in[15];
    const float* xproj_b  = (const float*)d_in[16];
    const float* dtw_b    = (const float*)d_in[17];
    const float* dtb_b    = (const float*)d_in[18];
    const float* Alog_b   = (const float*)d_in[19];
    const float* D_b      = (const float*)d_in[20];
    float* out = (float*)d_out;

    float *p_xz, *p_outpre, *p_dbl, *p_ydir;
    __nv_bfloat16 *p_xnh, *p_xnl, *p_wih, *p_wil, *p_woh, *p_wol;
    __nv_bfloat16 *p_xch, *p_xcl, *p_xpwh, *p_xpwl;
    cudaGetSymbolAddress((void**)&p_xz,     g_xz);
    cudaGetSymbolAddress((void**)&p_outpre, g_outpre);
    cudaGetSymbolAddress((void**)&p_dbl,    g_dbl);
    cudaGetSymbolAddress((void**)&p_ydir,   g_ydir);
    cudaGetSymbolAddress((void**)&p_xnh,    g_xnh);
    cudaGetSymbolAddress((void**)&p_xnl,    g_xnl);
    cudaGetSymbolAddress((void**)&p_wih,    g_wih);
    cudaGetSymbolAddress((void**)&p_wil,    g_wil);
    cudaGetSymbolAddress((void**)&p_woh,    g_woh);
    cudaGetSymbolAddress((void**)&p_wol,    g_wol);
    cudaGetSymbolAddress((void**)&p_xch,    g_xch);
    cudaGetSymbolAddress((void**)&p_xcl,    g_xcl);
    cudaGetSymbolAddress((void**)&p_xpwh,   g_xpwh);
    cudaGetSymbolAddress((void**)&p_xpwl,   g_xpwl);

    // 0. weight bf16 splits (in_proj, out_proj, padded x_proj)
    int wtot = 512 * 128 + 128 * 256 + 2 * NDBL * 256;
    k_wconv<<<(wtot + 255) / 256, 256>>>(in_proj, out_proj, xproj_f, xproj_b);

    // 1. LN1 + transpose + split
    k_ln1<<<MTOK / 64, 256>>>(x, ln1_w, ln1_b);

    // 2. in_proj: [32768,128] x [512,128]^T -> g_xz
    gemm_mma<DM, false><<<dim3(MTOK / 128, 4), 256>>>(p_xnh, p_xnl, p_wih, p_wil,
                                                      p_xz, 2 * DI);

    // 3. conv + silu + split, both dirs in one pass
    k_conv2<<<dim3(LL / 64, BB), 256>>>(conv_w_f, conv_b_f, conv_w_b, conv_b_b);

    // 4. x_proj per dir: [32768,256] x [40(pad128),256]^T -> g_dbl
    gemm_mma<DI, false><<<dim3(MTOK / 128, 1), 256>>>(
        p_xch, p_xcl, p_xpwh, p_xpwl, p_dbl, NDBL);
    gemm_mma<DI, false><<<dim3(MTOK / 128, 1), 256>>>(
        p_xch + (size_t)MTOK * DI, p_xcl + (size_t)MTOK * DI,
        p_xpwh + (size_t)128 * 256, p_xpwl + (size_t)128 * 256,
        p_dbl + (size_t)MTOK * NDBL, NDBL);

    // 5. dt precompute -> {r, cB}
    k_dt<<<dim3(MTOK / 64, 2), 256>>>(dtw_f, dtb_f, dtw_b, dtb_b);

    // 6-8. chunked selective scan
    k_scan1<<<dim3(NCH, BB, 2), 256>>>(Alog_f, Alog_b);
    k_scan2<<<2 * BB * NS, 256>>>();
    k_scan3<<<dim3(NCH, BB, 2), 256>>>(Alog_f, D_f, Alog_b, D_b);

    // 9. out_proj with fused (y_f + y_b) sum+split staging
    gemm_mma<DI, true><<<dim3(MTOK / 128, 1), 256>>>(
        p_ydir, p_ydir + (size_t)MTOK * DI, p_woh, p_wol, p_outpre, DM);

    // 10. residual + LN2 + transpose back
    k_ln2<<<MTOK / 64, 256>>>(ln2_w, ln2_b, out);
}

// round 8
// speedup vs baseline: 1.4085x; 1.0639x over previous
#include <cuda_runtime.h>
#include <cuda_bf16.h>
#include <cstdint>

// ---------------------------------------------------------------------------
// MambaLayer (bidirectional VideoMamba), B200 sm_100 — round 8
// inline-dt scans (no rcb), packed xc, BN=64 xproj, parallel conv
// ---------------------------------------------------------------------------

#define BB   4
#define DM   128
#define LL   8192
#define DI   256
#define NS   16
#define DTR  8
#define NDBL 40
#define MTOK (BB*LL)
#define CHUNK 64
#define NCH  (LL/CHUNK)

// ------------------------- scratch (static device mem) ---------------------
__device__ __nv_bfloat16  g_xnh   [MTOK*DM];
__device__ __nv_bfloat16  g_xnl   [MTOK*DM];
__device__ float          g_xz    [MTOK*2*DI];
__device__ float          g_dbl   [2][MTOK*NDBL];
__device__ uint32_t       g_xc32  [2][MTOK*DI];     // packed bf16 (hi | lo<<16)
__device__ float          g_ydir  [2][MTOK*DI];
__device__ float          g_hend  [2*NCH*BB*NS*DI];
__device__ float          g_P     [2*NCH*BB*NS*DI];
__device__ float          g_hinit [2*NCH*BB*NS*DI];
__device__ float          g_outpre[MTOK*DM];
__device__ __nv_bfloat16  g_wih[512*128],  g_wil[512*128];
__device__ __nv_bfloat16  g_woh[128*256],  g_wol[128*256];
__device__ __nv_bfloat16  g_xpwh[2][64*256], g_xpwl[2][64*256]; // rows>=40 zero

// ------------------------- math helpers -------------------------------------
__device__ __forceinline__ float siluf(float x) {
    return __fdividef(x, 1.f + __expf(-x));
}
__device__ __forceinline__ void mkpow(float r, float* w) {
    float r2 = r * r, r3 = r2 * r, r4 = r2 * r2;
    float r5 = r4 * r, r6 = r4 * r2, r7 = r4 * r3, r8 = r4 * r4;
    w[0]=r;  w[1]=r2; w[2]=r3; w[3]=r4; w[4]=r5; w[5]=r6; w[6]=r7; w[7]=r8;
    w[8]=r8*r; w[9]=r8*r2; w[10]=r8*r3; w[11]=r8*r4;
    w[12]=r8*r5; w[13]=r8*r6; w[14]=r8*r7; w[15]=r8*r8;
}
__device__ __forceinline__ void bsplit(float v, __nv_bfloat16& hi, __nv_bfloat16& lo) {
    hi = __float2bfloat16(v);
    lo = __float2bfloat16(v - __bfloat162float(hi));
}
__device__ __forceinline__ uint32_t pack2(__nv_bfloat16 a, __nv_bfloat16 b) {
    return (uint32_t)__bfloat16_as_ushort(a) | ((uint32_t)__bfloat16_as_ushort(b) << 16);
}
__device__ __forceinline__ float unpack_sum(uint32_t p) {
    __nv_bfloat16 h = __ushort_as_bfloat16((unsigned short)(p & 0xffffu));
    __nv_bfloat16 l = __ushort_as_bfloat16((unsigned short)(p >> 16));
    return __bfloat162float(h) + __bfloat162float(l);
}
// softplus pieces from a: e = exp(a); r = exp(-softplus(a)); dt = softplus(a)
__device__ __forceinline__ void dt_math(float a, float& r, float& dt) {
    float e = __expf(a);
    r = __fdividef(1.f, 1.f + e);
    if (a > 15.f)      dt = a;
    else if (a > -3.f) dt = __logf(1.f + e);
    else               dt = e * fmaf(e, fmaf(e, 0.33333334f, -0.5f), 1.f);
}

// ------------------------- weight convert -----------------------------------
__global__ void k_wconv(const float* __restrict__ wi, const float* __restrict__ wo,
                        const float* __restrict__ xpf, const float* __restrict__ xpb) {
    int i = blockIdx.x * 256 + threadIdx.x;
    if (i < 512 * 128) { bsplit(wi[i], g_wih[i], g_wil[i]); return; }
    int j = i - 512 * 128;
    if (j < 128 * 256) { bsplit(wo[j], g_woh[j], g_wol[j]); return; }
    int k = j - 128 * 256;
    if (k < 2 * 64 * 256) {
        int dir = k / (64 * 256);
        int idx = k - dir * 64 * 256;
        int n = idx >> 8;
        const float* src = dir ? xpb : xpf;
        float v = (n < NDBL) ? src[idx] : 0.f;
        bsplit(v, g_xpwh[dir][idx], g_xpwl[dir][idx]);
    }
}

// ------------------------- LN1 + transpose + bf16 split ---------------------
__global__ void k_ln1(const float* __restrict__ x,
                      const float* __restrict__ w, const float* __restrict__ bia) {
    __shared__ float s[DM][65];
    __shared__ float rs_[4][64], rq_[4][64];
    __shared__ float mu[64], rstd[64];
    int tid = threadIdx.x;
    int m0 = blockIdx.x * 64;
    int b  = m0 / LL;
    int l0 = m0 % LL;
#pragma unroll
    for (int i = 0; i < 32; i++) {
        int e = tid + i * 256;
        int l = e & 63, c = e >> 6;
        s[c][l] = x[(b * DM + c) * LL + l0 + l];
    }
    __syncthreads();
    {
        int tok = tid & 63, part = tid >> 6;
        float su = 0.f, sq = 0.f;
#pragma unroll
        for (int cc = 0; cc < 32; cc++) {
            float v = s[part * 32 + cc][tok];
            su += v; sq = fmaf(v, v, sq);
        }
        rs_[part][tok] = su; rq_[part][tok] = sq;
    }
    __syncthreads();
    if (tid < 64) {
        float su = rs_[0][tid] + rs_[1][tid] + rs_[2][tid] + rs_[3][tid];
        float sq = rq_[0][tid] + rq_[1][tid] + rq_[2][tid] + rq_[3][tid];
        float m = su * (1.f / DM);
        float var = sq * (1.f / DM) - m * m;
        mu[tid] = m; rstd[tid] = rsqrtf(var + 1e-5f);
    }
    __syncthreads();
#pragma unroll
    for (int i = 0; i < 32; i++) {
        int e = tid + i * 256;
        int c = e & 127, l = e >> 7;
        float v = s[c][l];
        int gi = (m0 + l) * DM + c;
        float vn = (v - mu[l]) * rstd[l] * w[c] + bia[c];
        bsplit(vn, g_xnh[gi], g_xnl[gi]);
    }
}

// ------------------------- mma.sync bf16-split GEMM -------------------------
// AMODE 0: A1/A2 bf16 hi/lo.  1: A1 packed uint32.  2: A1/A2 float, sum+split.
__device__ __forceinline__ void mma16816(float* c, const uint32_t* a, const uint32_t* b) {
    asm volatile(
        "mma.sync.aligned.m16n8k16.row.col.f32.bf16.bf16.f32 "
        "{%0,%1,%2,%3}, {%4,%5,%6,%7}, {%8,%9}, {%0,%1,%2,%3};"
        : "+f"(c[0]), "+f"(c[1]), "+f"(c[2]), "+f"(c[3])
        : "r"(a[0]), "r"(a[1]), "r"(a[2]), "r"(a[3]), "r"(b[0]), "r"(b[1]));
}

template<int KTOT, int BN, int AMODE>
__global__ __launch_bounds__(256) void gemm_mma(
        const void* __restrict__ A1, const void* __restrict__ A2,
        const __nv_bfloat16* __restrict__ Bh, const __nv_bfloat16* __restrict__ Bl,
        float* __restrict__ C, int Nn) {
    __shared__ uint32_t As[2][128][18];
    __shared__ uint32_t Bs[2][BN][18];
    const int tid = threadIdx.x;
    const int m0 = blockIdx.x * 128, n0 = blockIdx.y * BN;
    const int wid = tid >> 5, lane = tid & 31;
    constexpr int NI = (BN == 128) ? 4 : 2;
    const int wm0 = (BN == 128) ? (wid & 1) * 64 : (wid & 3) * 32;
    const int wn0 = (BN == 128) ? (wid >> 1) * 32 : (wid >> 2) * 32;
    const int gr = lane >> 2, cp = lane & 3;
    float acc[NI][4][4] = {};

    const int lrow = tid >> 1, lhalf = tid & 1;
    for (int k0 = 0; k0 < KTOT; k0 += 32) {
        // ---- stage A (hi/lo) ----
        if (AMODE == 0) {
#pragma unroll
            for (int sel = 0; sel < 2; sel++) {
                const __nv_bfloat16* src = sel ? (const __nv_bfloat16*)A2
                                               : (const __nv_bfloat16*)A1;
                const uint4* gp = (const uint4*)&src[(size_t)(m0 + lrow) * KTOT + k0 + lhalf * 16];
                uint4 v0 = gp[0], v1 = gp[1];
                uint32_t* d = &As[sel][lrow][lhalf * 8];
                d[0] = v0.x; d[1] = v0.y; d[2] = v0.z; d[3] = v0.w;
                d[4] = v1.x; d[5] = v1.y; d[6] = v1.z; d[7] = v1.w;
            }
        } else if (AMODE == 1) {
            const uint32_t* src = (const uint32_t*)A1;
            const uint4* gp = (const uint4*)&src[(size_t)(m0 + lrow) * KTOT + k0 + lhalf * 16];
            uint4 p0 = gp[0], p1 = gp[1], p2 = gp[2], p3 = gp[3];
            uint32_t pw[16] = {p0.x,p0.y,p0.z,p0.w, p1.x,p1.y,p1.z,p1.w,
                               p2.x,p2.y,p2.z,p2.w, p3.x,p3.y,p3.z,p3.w};
            uint32_t* dh = &As[0][lrow][lhalf * 8];
            uint32_t* dl = &As[1][lrow][lhalf * 8];
#pragma unroll
            for (int q = 0; q < 8; q++) {
                dh[q] = __byte_perm(pw[2*q], pw[2*q+1], 0x5410);
                dl[q] = __byte_perm(pw[2*q], pw[2*q+1], 0x7632);
            }
        } else {
            const float* Yf = (const float*)A1;
            const float* Yb = (const float*)A2;
            const float4* pf = (const float4*)&Yf[(size_t)(m0 + lrow) * KTOT + k0 + lhalf * 16];
            const float4* pb = (const float4*)&Yb[(size_t)(m0 + lrow) * KTOT + k0 + lhalf * 16];
            float v[16];
#pragma unroll
            for (int q = 0; q < 4; q++) {
                float4 a = pf[q], bq = pb[q];
                v[q*4+0] = a.x + bq.x; v[q*4+1] = a.y + bq.y;
                v[q*4+2] = a.z + bq.z; v[q*4+3] = a.w + bq.w;
            }
            uint32_t* dh = &As[0][lrow][lhalf * 8];
            uint32_t* dl = &As[1][lrow][lhalf * 8];
#pragma unroll
            for (int q = 0; q < 8; q++) {
                __nv_bfloat16 h0, l0, h1, l1;
                bsplit(v[2*q], h0, l0);
                bsplit(v[2*q+1], h1, l1);
                dh[q] = pack2(h0, h1);
                dl[q] = pack2(l0, l1);
            }
        }
        // ---- stage B (hi/lo) ----
        if (BN == 128 || tid < 2 * BN) {
#pragma unroll
            for (int sel = 0; sel < 2; sel++) {
                const __nv_bfloat16* src = sel ? Bl : Bh;
                const uint4* gp = (const uint4*)&src[(size_t)(n0 + lrow) * KTOT + k0 + lhalf * 16];
                uint4 v0 = gp[0], v1 = gp[1];
                uint32_t* d = &Bs[sel][lrow][lhalf * 8];
                d[0] = v0.x; d[1] = v0.y; d[2] = v0.z; d[3] = v0.w;
                d[4] = v1.x; d[5] = v1.y; d[6] = v1.z; d[7] = v1.w;
            }
        }
        __syncthreads();
#pragma unroll
        for (int pass = 0; pass < 3; pass++) {
            uint32_t (*pA)[18] = As[pass == 2 ? 1 : 0];
            uint32_t (*pB)[18] = Bs[pass == 1 ? 1 : 0];
#pragma unroll
            for (int k16 = 0; k16 < 2; k16++) {
                const int kp = k16 * 8;
                uint32_t a[NI][4], bf[4][2];
#pragma unroll
                for (int i = 0; i < NI; i++) {
                    int rbase = wm0 + 16 * i;
                    a[i][0] = pA[rbase + gr][kp + cp];
                    a[i][1] = pA[rbase + gr + 8][kp + cp];
                    a[i][2] = pA[rbase + gr][kp + cp + 4];
                    a[i][3] = pA[rbase + gr + 8][kp + cp + 4];
                }
#pragma unroll
                for (int j = 0; j < 4; j++) {
                    int brow = wn0 + 8 * j + gr;
                    bf[j][0] = pB[brow][kp + cp];
                    bf[j][1] = pB[brow][kp + cp + 4];
                }
#pragma unroll
                for (int i = 0; i < NI; i++)
#pragma unroll
                    for (int j = 0; j < 4; j++)
                        mma16816(acc[i][j], a[i], bf[j]);
            }
        }
        __syncthreads();
    }
#pragma unroll
    for (int i = 0; i < NI; i++) {
#pragma unroll
        for (int j = 0; j < 4; j++) {
            int row = m0 + wm0 + 16 * i + gr;
            int col = n0 + wn0 + 8 * j + cp * 2;
            if (col < Nn) {
                *(float2*)&C[(size_t)row * Nn + col] = make_float2(acc[i][j][0], acc[i][j][1]);
                *(float2*)&C[(size_t)(row + 8) * Nn + col] = make_float2(acc[i][j][2], acc[i][j][3]);
            }
        }
    }
}

// ------------------------- conv + silu + packed split, BOTH dirs ------------
__global__ void k_conv2(const float* __restrict__ cwf, const float* __restrict__ cbf,
                        const float* __restrict__ cwb, const float* __restrict__ cbb) {
    int d = threadIdx.x;
    int t0 = blockIdx.x * 16;
    int b = blockIdx.y;
    float wf0 = cwf[d*4], wf1 = cwf[d*4+1], wf2 = cwf[d*4+2], wf3 = cwf[d*4+3];
    float bf = cbf[d];
    float wb0 = cwb[d*4], wb1 = cwb[d*4+1], wb2 = cwb[d*4+2], wb3 = cwb[d*4+3];
    float bb = cbb[d];
    const float* xp = g_xz + (size_t)(b * LL) * 512 + d;
    float v[7];
#pragma unroll
    for (int j = 0; j < 7; j++) {
        int tt = t0 - 3 + j;
        v[j] = (tt >= 0 && tt < LL) ? xp[(size_t)tt * 512] : 0.f;
    }
#pragma unroll
    for (int i = 0; i < 16; i++) {
        int t = t0 + i;
        float f  = bf + wf0*v[0] + wf1*v[1] + wf2*v[2] + wf3*v[3];
        float bw = bb + wb0*v[6] + wb1*v[5] + wb2*v[4] + wb3*v[3];
        float xf = siluf(f), xb = siluf(bw);
        __nv_bfloat16 h, l;
        bsplit(xf, h, l);
        g_xc32[0][(size_t)(b * LL + t) * DI + d] = pack2(h, l);
        bsplit(xb, h, l);
        g_xc32[1][(size_t)(b * LL + (LL - 1 - t)) * DI + d] = pack2(h, l);
        v[0]=v[1]; v[1]=v[2]; v[2]=v[3]; v[3]=v[4]; v[4]=v[5]; v[5]=v[6];
        int tn = t + 4;
        v[6] = (tn < LL) ? xp[(size_t)tn * 512] : 0.f;
    }
}

// ------------------------- scan pass 1 (inline dt) --------------------------
__global__ void k_scan1(const float* __restrict__ Alog_f, const float* __restrict__ Alog_b,
                        const float* __restrict__ dtw_f, const float* __restrict__ dtb_f,
                        const float* __restrict__ dtw_b, const float* __restrict__ dtb_b) {
    int ch = blockIdx.x, b = blockIdx.y, dir = blockIdx.z, d = threadIdx.x;
    const float* Alog = dir ? Alog_b : Alog_f;
    const float* dtw  = dir ? dtw_b : dtw_f;
    float dtb = (dir ? dtb_b : dtb_f)[d];
    __shared__ __align__(16) float sd[CHUNK][24];     // dt-rank 8 + B 16
    int t0 = ch * CHUNK;
    const float* gsrc = g_dbl[dir] + (size_t)(b * LL + t0) * NDBL;
    for (int i = threadIdx.x; i < CHUNK * 6; i += 256) {
        int t = i / 6, q = i - t * 6;
        *((float4*)&sd[t][q * 4]) = *((const float4*)&gsrc[t * NDBL + q * 4]);
    }
    float Ad[NS], h[NS], wdt[DTR];
    bool fast = true;
#pragma unroll
    for (int n = 0; n < NS; n++) {
        Ad[n] = -__expf(Alog[d * NS + n]);
        fast = fast && (fabsf(Ad[n] + (float)(n + 1)) <= 1e-5f * (n + 1));
    }
#pragma unroll
    for (int i = 0; i < DTR; i++) wdt[i] = dtw[d * DTR + i];
#pragma unroll
    for (int n = 0; n < NS; n++) h[n] = 0.f;
    const uint32_t* xc = g_xc32[dir] + (size_t)(b * LL + t0) * DI + d;
    float rP = 1.f, S = 0.f;
    __syncthreads();
    if (fast) {
#pragma unroll 2
        for (int t = 0; t < CHUNK; t++) {
            const float* row = sd[t];
            float4 d0 = *(const float4*)&row[0];
            float4 d1 = *(const float4*)&row[4];
            float a = dtb;
            a = fmaf(wdt[0], d0.x, a); a = fmaf(wdt[1], d0.y, a);
            a = fmaf(wdt[2], d0.z, a); a = fmaf(wdt[3], d0.w, a);
            a = fmaf(wdt[4], d1.x, a); a = fmaf(wdt[5], d1.y, a);
            a = fmaf(wdt[6], d1.z, a); a = fmaf(wdt[7], d1.w, a);
            float r, dt; dt_math(a, r, dt);
            float cB = dt * unpack_sum(xc[(size_t)t * DI]);
            float4 B0 = *(const float4*)&row[8],  B1 = *(const float4*)&row[12];
            float4 B2 = *(const float4*)&row[16], B3 = *(const float4*)&row[20];
            float Bv[16] = {B0.x,B0.y,B0.z,B0.w, B1.x,B1.y,B1.z,B1.w,
                            B2.x,B2.y,B2.z,B2.w, B3.x,B3.y,B3.z,B3.w};
            float wv[NS];
            mkpow(r, wv);
            rP *= r;
#pragma unroll
            for (int n = 0; n < NS; n++)
                h[n] = fmaf(wv[n], h[n], cB * Bv[n]);
        }
    } else {
        for (int t = 0; t < CHUNK; t++) {
            const float* row = sd[t];
            float a = dtb;
#pragma unroll
            for (int i = 0; i < DTR; i++) a = fmaf(wdt[i], row[i], a);
            float r, dt; dt_math(a, r, dt);
            float cB = dt * unpack_sum(xc[(size_t)t * DI]);
            S += dt;
#pragma unroll
            for (int n = 0; n < NS; n++)
                h[n] = fmaf(__expf(dt * Ad[n]), h[n], cB * row[8 + n]);
        }
    }
    int base = ((dir * NCH + ch) * BB + b) * NS;
    if (fast) {
        float pw[NS];
        mkpow(rP, pw);
#pragma unroll
        for (int n = 0; n < NS; n++) {
            g_hend[(base + n) * DI + d] = h[n];
            g_P[(base + n) * DI + d]    = pw[n];
        }
    } else {
#pragma unroll
        for (int n = 0; n < NS; n++) {
            g_hend[(base + n) * DI + d] = h[n];
            g_P[(base + n) * DI + d]    = __expf(Ad[n] * S);
        }
    }
}

// ------------------------- scan pass 2 --------------------------------------
__global__ void k_scan2() {
    int d = threadIdx.x;
    int n   = blockIdx.x & 15;
    int b   = (blockIdx.x >> 4) & 3;
    int dir = blockIdx.x >> 6;
    float hs = 0.f;
    for (int ch = 0; ch < NCH; ch++) {
        int idx = (((dir * NCH + ch) * BB + b) * NS + n) * DI + d;
        g_hinit[idx] = hs;
        hs = fmaf(g_P[idx], hs, g_hend[idx]);
    }
}

// ------------------------- scan pass 3 (inline dt, emit y) ------------------
__global__ void k_scan3(const float* __restrict__ Alog_f, const float* __restrict__ Dsk_f,
                        const float* __restrict__ Alog_b, const float* __restrict__ Dsk_b,
                        const float* __restrict__ dtw_f, const float* __restrict__ dtb_f,
                        const float* __restrict__ dtw_b, const float* __restrict__ dtb_b) {
    int ch = blockIdx.x, b = blockIdx.y, dir = blockIdx.z, d = threadIdx.x;
    const float* Alog = dir ? Alog_b : Alog_f;
    const float* dtw  = dir ? dtw_b : dtw_f;
    float dtb = (dir ? dtb_b : dtb_f)[d];
    float Dd  = (dir ? Dsk_b : Dsk_f)[d];
    __shared__ __align__(16) float sd[CHUNK][40];     // dt 8 + B 16 + C 16
    int t0 = ch * CHUNK;
    const float* gsrc = g_dbl[dir] + (size_t)(b * LL + t0) * NDBL;
    for (int i = threadIdx.x; i < CHUNK * 10; i += 256) {
        int t = i / 10, q = i - t * 10;
        *((float4*)&sd[t][q * 4]) = *((const float4*)&gsrc[t * NDBL + q * 4]);
    }
    float Ad[NS], h[NS], wdt[DTR];
    bool fast = true;
#pragma unroll
    for (int n = 0; n < NS; n++) {
        Ad[n] = -__expf(Alog[d * NS + n]);
        fast = fast && (fabsf(Ad[n] + (float)(n + 1)) <= 1e-5f * (n + 1));
    }
#pragma unroll
    for (int i = 0; i < DTR; i++) wdt[i] = dtw[d * DTR + i];
    int base = ((dir * NCH + ch) * BB + b) * NS;
#pragma unroll
    for (int n = 0; n < NS; n++) h[n] = g_hinit[(base + n) * DI + d];
    const uint32_t* xc = g_xc32[dir] + (size_t)(b * LL + t0) * DI + d;
    const float* xzz = g_xz + (size_t)b * LL * 512 + DI + d;
    float* yout = g_ydir[dir] + (size_t)b * LL * DI + d;
    __syncthreads();
    if (fast) {
#pragma unroll 2
        for (int t = 0; t < CHUNK; t++) {
            const float* row = sd[t];
            float4 d0 = *(const float4*)&row[0];
            float4 d1 = *(const float4*)&row[4];
            float a = dtb;
            a = fmaf(wdt[0], d0.x, a); a = fmaf(wdt[1], d0.y, a);
            a = fmaf(wdt[2], d0.z, a); a = fmaf(wdt[3], d0.w, a);
            a = fmaf(wdt[4], d1.x, a); a = fmaf(wdt[5], d1.y, a);
            a = fmaf(wdt[6], d1.z, a); a = fmaf(wdt[7], d1.w, a);
            float r, dt; dt_math(a, r, dt);
            float xv = unpack_sum(xc[(size_t)t * DI]);
            float cB = dt * xv;
            float4 B0 = *(const float4*)&row[8],  B1 = *(const float4*)&row[12];
            float4 B2 = *(const float4*)&row[16], B3 = *(const float4*)&row[20];
            float4 C0 = *(const float4*)&row[24], C1 = *(const float4*)&row[28];
            float4 C2 = *(const float4*)&row[32], C3 = *(const float4*)&row[36];
            float Bv[16] = {B0.x,B0.y,B0.z,B0.w, B1.x,B1.y,B1.z,B1.w,
                            B2.x,B2.y,B2.z,B2.w, B3.x,B3.y,B3.z,B3.w};
            float Cv[16] = {C0.x,C0.y,C0.z,C0.w, C1.x,C1.y,C1.z,C1.w,
                            C2.x,C2.y,C2.z,C2.w, C3.x,C3.y,C3.z,C3.w};
            float wv[NS];
            mkpow(r, wv);
            float y = 0.f;
#pragma unroll
            for (int n = 0; n < NS; n++) {
                h[n] = fmaf(wv[n], h[n], cB * Bv[n]);
                y = fmaf(h[n], Cv[n], y);
            }
            int torig = dir ? (LL - 1 - (t0 + t)) : (t0 + t);
            float zv = xzz[(size_t)torig * 512];
            yout[(size_t)torig * DI] = (y + xv * Dd) * siluf(zv);
        }
    } else {
        for (int t = 0; t < CHUNK; t++) {
            const float* row = sd[t];
            float a = dtb;
#pragma unroll
            for (int i = 0; i < DTR; i++) a = fmaf(wdt[i], row[i], a);
            float r, dt; dt_math(a, r, dt);
            float xv = unpack_sum(xc[(size_t)t * DI]);
            float cB = dt * xv;
            float y = 0.f;
#pragma unroll
            for (int n = 0; n < NS; n++) {
                h[n] = fmaf(__expf(dt * Ad[n]), h[n], cB * row[8 + n]);
                y = fmaf(h[n], row[24 + n], y);
            }
            int torig = dir ? (LL - 1 - (t0 + t)) : (t0 + t);
            float zv = xzz[(size_t)torig * 512];
            yout[(size_t)torig * DI] = (y + xv * Dd) * siluf(zv);
        }
    }
}

// ------------------------- LN2 + residual + transpose back ------------------
__global__ void k_ln2(const float* __restrict__ x,
                      const float* __restrict__ w, const float* __restrict__ bia,
                      float* __restrict__ out) {
    __shared__ float s[DM][65];
    __shared__ float rs_[4][64], rq_[4][64];
    __shared__ float mu[64], rstd[64];
    int tid = threadIdx.x;
    int m0 = blockIdx.x * 64;
    int b  = m0 / LL;
    int l0 = m0 % LL;
#pragma unroll
    for (int i = 0; i < 32; i++) {
        int e = tid + i * 256;
        int c = e & 127, l = e >> 7;
        s[c][l] = g_outpre[(m0 + l) * DM + c];
    }
    __syncthreads();
#pragma unroll
    for (int i = 0; i < 32; i++) {
        int e = tid + i * 256;
        int l = e & 63, c = e >> 6;
        s[c][l] += x[(b * DM + c) * LL + l0 + l];
    }
    __syncthreads();
    {
        int tok = tid & 63, part = tid >> 6;
        float su = 0.f, sq = 0.f;
#pragma unroll
        for (int cc = 0; cc < 32; cc++) {
            float v = s[part * 32 + cc][tok];
            su += v; sq = fmaf(v, v, sq);
        }
        rs_[part][tok] = su; rq_[part][tok] = sq;
    }
    __syncthreads();
    if (tid < 64) {
        float su = rs_[0][tid] + rs_[1][tid] + rs_[2][tid] + rs_[3][tid];
        float sq = rq_[0][tid] + rq_[1][tid] + rq_[2][tid] + rq_[3][tid];
        float m = su * (1.f / DM);
        float var = sq * (1.f / DM) - m * m;
        mu[tid] = m; rstd[tid] = rsqrtf(var + 1e-5f);
    }
    __syncthreads();
#pragma unroll
    for (int i = 0; i < 32; i++) {
        int e = tid + i * 256;
        int l = e & 63, c = e >> 6;
        out[(b * DM + c) * LL + l0 + l] = (s[c][l] - mu[l]) * rstd[l] * w[c] + bia[c];
    }
}

// ------------------------- launch ------------------------------------------
extern "C" void kernel_launch(void* const* d_in, const int* in_sizes, int n_in,
                              void* d_out, int out_size) {
    const float* x        = (const float*)d_in[0];
    const float* ln1_w    = (const float*)d_in[1];
    const float* ln1_b    = (const float*)d_in[2];
    const float* ln2_w    = (const float*)d_in[3];
    const float* ln2_b    = (const float*)d_in[4];
    const float* in_proj  = (const float*)d_in[5];
    const float* out_proj = (const float*)d_in[6];
    const float* conv_w_f = (const float*)d_in[7];
    const float* conv_b_f = (const float*)d_in[8];
    const float* xproj_f  = (const float*)d_in[9];
    const float* dtw_f    = (const float*)d_in[10];
    const float* dtb_f    = (const float*)d_in[11];
    const float* Alog_f   = (const float*)d_in[12];
    const float* D_f      = (const float*)d_in[13];
    const float* conv_w_b = (const float*)d_in[14];
    const float* conv_b_b = (const float*)d_in[15];
    const float* xproj_b  = (const float*)d_in[16];
    const float* dtw_b    = (const float*)d_in[17];
    const float* dtb_b    = (const float*)d_in[18];
    const float* Alog_b   = (const float*)d_in[19];
    const float* D_b      = (const float*)d_in[20];
    float* out = (float*)d_out;

    float *p_xz, *p_outpre, *p_dbl, *p_ydir;
    __nv_bfloat16 *p_xnh, *p_xnl, *p_wih, *p_wil, *p_woh, *p_wol, *p_xpwh, *p_xpwl;
    uint32_t *p_xc32;
    cudaGetSymbolAddress((void**)&p_xz,     g_xz);
    cudaGetSymbolAddress((void**)&p_outpre, g_outpre);
    cudaGetSymbolAddress((void**)&p_dbl,    g_dbl);
    cudaGetSymbolAddress((void**)&p_ydir,   g_ydir);
    cudaGetSymbolAddress((void**)&p_xnh,    g_xnh);
    cudaGetSymbolAddress((void**)&p_xnl,    g_xnl);
    cudaGetSymbolAddress((void**)&p_wih,    g_wih);
    cudaGetSymbolAddress((void**)&p_wil,    g_wil);
    cudaGetSymbolAddress((void**)&p_woh,    g_woh);
    cudaGetSymbolAddress((void**)&p_wol,    g_wol);
    cudaGetSymbolAddress((void**)&p_xpwh,   g_xpwh);
    cudaGetSymbolAddress((void**)&p_xpwl,   g_xpwl);
    cudaGetSymbolAddress((void**)&p_xc32,   g_xc32);

    // 0. weight bf16 splits
    int wtot = 512 * 128 + 128 * 256 + 2 * 64 * 256;
    k_wconv<<<(wtot + 255) / 256, 256>>>(in_proj, out_proj, xproj_f, xproj_b);

    // 1. LN1 + transpose + split
    k_ln1<<<MTOK / 64, 256>>>(x, ln1_w, ln1_b);

    // 2. in_proj: [32768,128] x [512,128]^T -> g_xz
    gemm_mma<DM, 128, 0><<<dim3(MTOK / 128, 4), 256>>>(p_xnh, p_xnl, p_wih, p_wil,
                                                       p_xz, 2 * DI);

    // 3. conv + silu + packed split, both dirs
    k_conv2<<<dim3(LL / 16, BB), 256>>>(conv_w_f, conv_b_f, conv_w_b, conv_b_b);

    // 4. x_proj per dir (BN=64, packed A): -> g_dbl
    gemm_mma<DI, 64, 1><<<dim3(MTOK / 128, 1), 256>>>(
        p_xc32, nullptr, p_xpwh, p_xpwl, p_dbl, NDBL);
    gemm_mma<DI, 64, 1><<<dim3(MTOK / 128, 1), 256>>>(
        p_xc32 + (size_t)MTOK * DI, nullptr,
        p_xpwh + (size_t)64 * 256, p_xpwl + (size_t)64 * 256,
        p_dbl + (size_t)MTOK * NDBL, NDBL);

    // 5-7. chunked selective scan (dt inline)
    k_scan1<<<dim3(NCH, BB, 2), 256>>>(Alog_f, Alog_b, dtw_f, dtb_f, dtw_b, dtb_b);
    k_scan2<<<2 * BB * NS, 256>>>();
    k_scan3<<<dim3(NCH, BB, 2), 256>>>(Alog_f, D_f, Alog_b, D_b,
                                       dtw_f, dtb_f, dtw_b, dtb_b);

    // 8. out_proj with fused (y_f + y_b) sum+split staging
    gemm_mma<DI, 128, 2><<<dim3(MTOK / 128, 1), 256>>>(
        p_ydir, p_ydir + (size_t)MTOK * DI, p_woh, p_wol, p_outpre, DM);

    // 9. residual + LN2 + transpose back
    k_ln2<<<MTOK / 64, 256>>>(x, ln2_w, ln2_b, out);
}